// round 7
// baseline (speedup 1.0000x reference)
#include <cuda_runtime.h>
#include <cuda_fp16.h>
#include <stdint.h>

#define NTOK 4096
#define CDIM 64
#define BM   128
#define BN   64
#define NITER (NTOK / BN)       // 64
#define NPROB 18
#define L2E  1.4426950408889634f

// ---------------------------------------------------------------------------
// Device scratch (static __device__ arrays: allocation-free per harness rules)
// ---------------------------------------------------------------------------
__device__ __half g_Qhi[3 * 2 * NTOK * CDIM];   // [branch][b][n][c] * log2e, hi
__device__ __half g_Qlo[3 * 2 * NTOK * CDIM];   // residual lo
__device__ __half g_KThi[3 * 2 * NTOK * CDIM];  // [kstream][b][j][c], hi
__device__ __half g_KTlo[3 * 2 * NTOK * CDIM];  // lo
__device__ __half g_Vh [3 * 2 * CDIM * NTOK];   // [branch][b][c][j]
__device__ float  g_O  [NPROB * NTOK * CDIM];   // [pidx][i][c] attention out

// ---------------------------------------------------------------------------
// Preprocessing
// ---------------------------------------------------------------------------
__global__ void prep_q(const float* __restrict__ q0, const float* __restrict__ q1,
                       const float* __restrict__ q2) {
    int z = blockIdx.y;
    const float* src = (z == 0) ? q0 : (z == 1) ? q1 : q2;
    int i = blockIdx.x * blockDim.x + threadIdx.x;     // [0, 524288)
    float v = src[i] * L2E;
    __half h = __float2half_rn(v);
    size_t o = (size_t)z * 2 * NTOK * CDIM + i;
    g_Qhi[o] = h;
    g_Qlo[o] = __float2half_rn(v - __half2float(h));
}

__global__ void prep_v(const float* __restrict__ v0, const float* __restrict__ v1,
                       const float* __restrict__ v2) {
    int z = blockIdx.y;
    const float* src = (z == 0) ? v0 : (z == 1) ? v1 : v2;
    int i = blockIdx.x * blockDim.x + threadIdx.x;
    g_Vh[(size_t)z * 2 * CDIM * NTOK + i] = __float2half_rn(src[i]);
}

// k [b][c][j] -> kT [j][c], hi/lo split. 32x32 tiles, block (32,8).
__global__ void prep_k(const float* __restrict__ k0, const float* __restrict__ k1,
                       const float* __restrict__ k2) {
    __shared__ float tile[32][33];
    int zb = blockIdx.z;
    int ks = zb >> 1, b = zb & 1;
    const float* src = ((ks == 0) ? k0 : (ks == 1) ? k1 : k2) + (size_t)b * CDIM * NTOK;
    int j0 = blockIdx.x * 32, c0 = blockIdx.y * 32;
    int tx = threadIdx.x, ty = threadIdx.y;
#pragma unroll
    for (int yy = 0; yy < 32; yy += 8)
        tile[ty + yy][tx] = src[(size_t)(c0 + ty + yy) * NTOK + j0 + tx];
    __syncthreads();
    size_t dstbase = ((size_t)ks * 2 + b) * NTOK * CDIM;
#pragma unroll
    for (int yy = 0; yy < 32; yy += 8) {
        int jl = ty + yy;
        float v = tile[tx][jl];
        __half h = __float2half_rn(v);
        size_t o = dstbase + (size_t)(j0 + jl) * CDIM + c0 + tx;
        g_KThi[o] = h;
        g_KTlo[o] = __float2half_rn(v - __half2float(h));
    }
}

// ---------------------------------------------------------------------------
// Fast exp2 (FMA/ALU pipes; avoids MUFU.EX2 throughput wall). x <= 0.
// ---------------------------------------------------------------------------
__device__ __forceinline__ float exp2_fast(float x) {
    x = fmaxf(x, -120.0f);
    float r  = __fadd_rn(x, 12582912.0f);
    float k  = __fadd_rn(r, -12582912.0f);
    int   ik = __float_as_int(r) - 0x4B400000;
    float f  = x - k;                              // [-0.5, 0.5]
    float p  = 1.333355815e-3f;
    p = fmaf(p, f, 9.618129107e-3f);
    p = fmaf(p, f, 5.550410866e-2f);
    p = fmaf(p, f, 2.402265069e-1f);
    p = fmaf(p, f, 6.931471806e-1f);
    p = fmaf(p, f, 1.0f);
    return __int_as_float(__float_as_int(p) + (ik << 23));
}

__device__ __forceinline__ uint32_t pack_h2(float a, float b) {
    __half2 h = __floats2half2_rn(a, b);
    return *reinterpret_cast<uint32_t*>(&h);
}
__device__ __forceinline__ uint32_t ld32h(const __half* p) {
    return *reinterpret_cast<const uint32_t*>(p);
}
__device__ __forceinline__ void cp_async16(uint32_t saddr, const void* g) {
    asm volatile("cp.async.cg.shared.global [%0], [%1], 16;" :: "r"(saddr), "l"(g));
}

#define MMA16816(D, A, B0, B1)                                                        \
    asm volatile("mma.sync.aligned.m16n8k16.row.col.f32.f16.f16.f32 "                 \
                 "{%0,%1,%2,%3},{%4,%5,%6,%7},{%8,%9},{%0,%1,%2,%3};"                 \
                 : "+f"((D)[0]), "+f"((D)[1]), "+f"((D)[2]), "+f"((D)[3])             \
                 : "r"((A)[0]), "r"((A)[1]), "r"((A)[2]), "r"((A)[3]),                \
                   "r"(B0), "r"(B1))

// ---------------------------------------------------------------------------
// Flash attention. grid (32 q-tiles, 18 problems), 256 thr (8 warps, 16 q-rows
// each). Per 64-col iteration: S = Qhi*Khi + Qlo*Khi + Qhi*Klo (fp32 acc);
// online base-2 softmax; P(f16) x V via MMA. O -> g_O.
// Smem: double buffer x 3 tiles [64][72] half = 55296 B.
// ---------------------------------------------------------------------------
#define TILE_H 4608                 // halves per tile (64*72)
#define BUF_H  (3 * TILE_H)         // halves per buffer
#define SMEM_FLASH (2 * BUF_H * 2)  // bytes = 55296

__global__ void __launch_bounds__(256) flash_kernel() {
    extern __shared__ __half sm[];
    const int tid = threadIdx.x;
    const int wi = tid >> 5, lane = tid & 31;
    const int g = lane >> 2, t = lane & 3;
    const int pidx = blockIdx.y;
    const int br = pidx / 6, rem = pidx % 6;
    const int ks = rem >> 1, b = rem & 1;
    const int i0 = blockIdx.x * BM + wi * 16;

    const size_t qoff = ((size_t)(br * 2 + b)) * NTOK * CDIM;
    const size_t koff = ((size_t)(ks * 2 + b)) * NTOK * CDIM;
    const size_t voff = ((size_t)(br * 2 + b)) * CDIM * NTOK;

    const uint32_t smbase = (uint32_t)__cvta_generic_to_shared(sm);

    // Q fragments (persist across the whole loop)
    uint32_t qh[4][4], ql[4][4];
    {
        const __half* Qh = g_Qhi + qoff;
        const __half* Ql = g_Qlo + qoff;
#pragma unroll
        for (int kc = 0; kc < 4; kc++) {
            int c0 = kc * 16 + 2 * t;
            const __half* r0h = Qh + (size_t)(i0 + g) * 64 + c0;
            const __half* r1h = Qh + (size_t)(i0 + g + 8) * 64 + c0;
            const __half* r0l = Ql + (size_t)(i0 + g) * 64 + c0;
            const __half* r1l = Ql + (size_t)(i0 + g + 8) * 64 + c0;
            qh[kc][0] = ld32h(r0h);     qh[kc][1] = ld32h(r1h);
            qh[kc][2] = ld32h(r0h + 8); qh[kc][3] = ld32h(r1h + 8);
            ql[kc][0] = ld32h(r0l);     ql[kc][1] = ld32h(r1l);
            ql[kc][2] = ld32h(r0l + 8); ql[kc][3] = ld32h(r1l + 8);
        }
    }

    float m_a = -1e30f, m_b = -1e30f, l_a = 0.0f, l_b = 0.0f;
    float acc[8][4];
#pragma unroll
    for (int n = 0; n < 8; n++)
#pragma unroll
        for (int q = 0; q < 4; q++) acc[n][q] = 0.0f;

    auto issue = [&](int bb, int jt) {
#pragma unroll
        for (int t3 = 0; t3 < 3; t3++) {
#pragma unroll
            for (int r = 0; r < 2; r++) {
                int v = tid + 256 * r;
                int row = v >> 3, c8 = v & 7;
                int soff = bb * BUF_H + t3 * TILE_H + row * 72 + c8 * 8;
                const __half* gp;
                if (t3 == 0)      gp = g_KThi + koff + (size_t)(jt + row) * 64 + c8 * 8;
                else if (t3 == 1) gp = g_KTlo + koff + (size_t)(jt + row) * 64 + c8 * 8;
                else              gp = g_Vh  + voff + (size_t)row * 4096 + jt + c8 * 8;
                cp_async16(smbase + soff * 2, gp);
            }
        }
    };

    issue(0, 0);
    asm volatile("cp.async.commit_group;");

#pragma unroll 1
    for (int it = 0; it < NITER; it++) {
        if (it < NITER - 1) {
            issue((it + 1) & 1, (it + 1) * BN);
            asm volatile("cp.async.commit_group;");
            asm volatile("cp.async.wait_group 1;" ::: "memory");
        } else {
            asm volatile("cp.async.wait_group 0;" ::: "memory");
        }
        __syncthreads();

        const __half* sKh = sm + (it & 1) * BUF_H;
        const __half* sV  = sKh + 2 * TILE_H;

        float S[8][4];
#pragma unroll
        for (int n = 0; n < 8; n++)
#pragma unroll
            for (int q = 0; q < 4; q++) S[n][q] = 0.0f;

        // GEMM1: S[16 x 64j] = Q[16 x 64c] * K^T
#pragma unroll
        for (int kc = 0; kc < 4; kc++) {
#pragma unroll
            for (int nc = 0; nc < 8; nc++) {
                const __half* kp = sKh + (8 * nc + g) * 72 + kc * 16 + 2 * t;
                uint32_t bh0 = ld32h(kp), bh1 = ld32h(kp + 8);
                const __half* lp = kp + TILE_H;
                uint32_t bl0 = ld32h(lp), bl1 = ld32h(lp + 8);
                MMA16816(S[nc], qh[kc], bh0, bh1);
                MMA16816(S[nc], ql[kc], bh0, bh1);
                MMA16816(S[nc], qh[kc], bl0, bl1);
            }
        }

        // Online softmax (base 2; log2e already folded into Q)
        float rmax_a = -1e30f, rmax_b = -1e30f;
#pragma unroll
        for (int nc = 0; nc < 8; nc++) {
            rmax_a = fmaxf(rmax_a, fmaxf(S[nc][0], S[nc][1]));
            rmax_b = fmaxf(rmax_b, fmaxf(S[nc][2], S[nc][3]));
        }
        rmax_a = fmaxf(rmax_a, __shfl_xor_sync(0xffffffffu, rmax_a, 1));
        rmax_a = fmaxf(rmax_a, __shfl_xor_sync(0xffffffffu, rmax_a, 2));
        rmax_b = fmaxf(rmax_b, __shfl_xor_sync(0xffffffffu, rmax_b, 1));
        rmax_b = fmaxf(rmax_b, __shfl_xor_sync(0xffffffffu, rmax_b, 2));

        float mna = fmaxf(m_a, rmax_a), mnb = fmaxf(m_b, rmax_b);
        float sca = exp2_fast(m_a - mna), scb = exp2_fast(m_b - mnb);
        m_a = mna; m_b = mnb;
        l_a *= sca; l_b *= scb;
#pragma unroll
        for (int nc = 0; nc < 8; nc++) {
            acc[nc][0] *= sca; acc[nc][1] *= sca;
            acc[nc][2] *= scb; acc[nc][3] *= scb;
        }
#pragma unroll
        for (int nc = 0; nc < 8; nc++) {
            S[nc][0] = exp2_fast(S[nc][0] - m_a);
            S[nc][1] = exp2_fast(S[nc][1] - m_a);
            S[nc][2] = exp2_fast(S[nc][2] - m_b);
            S[nc][3] = exp2_fast(S[nc][3] - m_b);
            l_a += S[nc][0] + S[nc][1];
            l_b += S[nc][2] + S[nc][3];
        }

        // GEMM2: acc[16 x 64c] += P[16 x 64j] * V^T  (V stored [c][j] = B col-major)
#pragma unroll
        for (int kj = 0; kj < 4; kj++) {
            uint32_t pa[4];
            pa[0] = pack_h2(S[2 * kj][0],     S[2 * kj][1]);
            pa[1] = pack_h2(S[2 * kj][2],     S[2 * kj][3]);
            pa[2] = pack_h2(S[2 * kj + 1][0], S[2 * kj + 1][1]);
            pa[3] = pack_h2(S[2 * kj + 1][2], S[2 * kj + 1][3]);
#pragma unroll
            for (int nc = 0; nc < 8; nc++) {
                const __half* vp = sV + (8 * nc + g) * 72 + kj * 16 + 2 * t;
                uint32_t v0 = ld32h(vp), v1 = ld32h(vp + 8);
                MMA16816(acc[nc], pa, v0, v1);
            }
        }
        __syncthreads();
    }

    // FIX: l_a/l_b are partial (this thread covers only its t-lane's columns);
    // the full row denominator is the sum across the 4 lanes of the group.
    l_a += __shfl_xor_sync(0xffffffffu, l_a, 1);
    l_a += __shfl_xor_sync(0xffffffffu, l_a, 2);
    l_b += __shfl_xor_sync(0xffffffffu, l_b, 1);
    l_b += __shfl_xor_sync(0xffffffffu, l_b, 2);

    // Normalize and dump O tile (fp32, [i][c], float2 stores coalesced)
    float ia = 1.0f / l_a, ib = 1.0f / l_b;
    float* Ob = g_O + (size_t)pidx * NTOK * CDIM;
#pragma unroll
    for (int nc = 0; nc < 8; nc++) {
        float2 va = make_float2(acc[nc][0] * ia, acc[nc][1] * ia);
        float2 vb = make_float2(acc[nc][2] * ib, acc[nc][3] * ib);
        *reinterpret_cast<float2*>(&Ob[(size_t)(i0 + g) * 64 + nc * 8 + 2 * t]) = va;
        *reinterpret_cast<float2*>(&Ob[(size_t)(i0 + g + 8) * 64 + nc * 8 + 2 * t]) = vb;
    }
}

// ---------------------------------------------------------------------------
// Epilogue: out[br][b][ks*64+oc][i] = sum_c O[pidx][i][c]*w[oc][c] + bias[oc] + x[b][oc][i]
// grid (32, 18), 128 threads: each thread owns one token i, loops 64 oc.
// ---------------------------------------------------------------------------
__global__ void __launch_bounds__(128) conv_epilogue(
    const float* __restrict__ w0, const float* __restrict__ w1, const float* __restrict__ w2,
    const float* __restrict__ bi0, const float* __restrict__ bi1, const float* __restrict__ bi2,
    const float* __restrict__ x0, const float* __restrict__ x1, const float* __restrict__ x2,
    float* __restrict__ out)
{
    __shared__ __align__(16) float w_s[4096];
    __shared__ float bs[64];
    const int tid = threadIdx.x;
    const int pidx = blockIdx.y;
    const int br = pidx / 6, rem = pidx % 6;
    const int ks = rem >> 1, b = rem & 1;

    const float* w  = (br == 0) ? w0  : (br == 1) ? w1  : w2;
    const float* bi = (br == 0) ? bi0 : (br == 1) ? bi1 : bi2;
    const float* x  = (br == 0) ? x0  : (br == 1) ? x1  : x2;

#pragma unroll
    for (int r = 0; r < 8; r++) {
        int idx4 = tid + 128 * r;
        reinterpret_cast<float4*>(w_s)[idx4] = reinterpret_cast<const float4*>(w)[idx4];
    }
    if (tid < 64) bs[tid] = bi[tid];
    __syncthreads();

    const int i = blockIdx.x * 128 + tid;
    const float* Orow = g_O + (size_t)pidx * NTOK * CDIM + (size_t)i * 64;
    float4 ov[16];
#pragma unroll
    for (int c4 = 0; c4 < 16; c4++)
        ov[c4] = reinterpret_cast<const float4*>(Orow)[c4];

    const float* xr = x + (size_t)b * CDIM * NTOK + i;
    float* orow = out + (size_t)br * (2 * 192 * NTOK) + (size_t)b * (192 * NTOK)
                      + (size_t)ks * (64 * NTOK) + i;

#pragma unroll 4
    for (int oc = 0; oc < 64; oc++) {
        float a = bs[oc];
        const float4* wr = reinterpret_cast<const float4*>(w_s + oc * 64);
#pragma unroll
        for (int c4 = 0; c4 < 16; c4++) {
            float4 w4 = wr[c4];
            a = fmaf(ov[c4].x, w4.x, a);
            a = fmaf(ov[c4].y, w4.y, a);
            a = fmaf(ov[c4].z, w4.z, a);
            a = fmaf(ov[c4].w, w4.w, a);
        }
        orow[(size_t)oc * NTOK] = a + xr[(size_t)oc * NTOK];
    }
}

// ---------------------------------------------------------------------------
// Launch. Inputs are in setup_inputs() dict-insertion order:
//  0 poi_q  1 poi_k  2 poi_v  3 x_poi
//  4 point_q 5 point_k 6 point_v 7 x_point
//  8 pop_q  9 pop_k  10 pop_v 11 x_pop
//  12 w_poi 13 b_poi 14 w_point 15 b_point 16 w_pop 17 b_pop
// ---------------------------------------------------------------------------
extern "C" void kernel_launch(void* const* d_in, const int* in_sizes, int n_in,
                              void* d_out, int out_size) {
    const float* poi_q   = (const float*)d_in[0];
    const float* poi_k   = (const float*)d_in[1];
    const float* poi_v   = (const float*)d_in[2];
    const float* x_poi   = (const float*)d_in[3];
    const float* point_q = (const float*)d_in[4];
    const float* point_k = (const float*)d_in[5];
    const float* point_v = (const float*)d_in[6];
    const float* x_point = (const float*)d_in[7];
    const float* pop_q   = (const float*)d_in[8];
    const float* pop_k   = (const float*)d_in[9];
    const float* pop_v   = (const float*)d_in[10];
    const float* x_pop   = (const float*)d_in[11];
    const float* w_poi   = (const float*)d_in[12];
    const float* b_poi   = (const float*)d_in[13];
    const float* w_point = (const float*)d_in[14];
    const float* b_point = (const float*)d_in[15];
    const float* w_pop   = (const float*)d_in[16];
    const float* b_pop   = (const float*)d_in[17];
    float* out = (float*)d_out;

    // Idempotent; first (uncaptured) correctness call sets it persistently.
    cudaFuncSetAttribute(flash_kernel, cudaFuncAttributeMaxDynamicSharedMemorySize,
                         SMEM_FLASH);

    prep_q<<<dim3(2048, 3), 256>>>(poi_q, point_q, pop_q);
    prep_v<<<dim3(2048, 3), 256>>>(poi_v, point_v, pop_v);
    prep_k<<<dim3(128, 2, 6), dim3(32, 8)>>>(poi_k, point_k, pop_k);
    flash_kernel<<<dim3(32, 18), 256, SMEM_FLASH>>>();
    conv_epilogue<<<dim3(32, 18), 128>>>(w_poi, w_point, w_pop,
                                         b_poi, b_point, b_pop,
                                         x_poi, x_point, x_pop, out);
}

// round 8
// speedup vs baseline: 1.1651x; 1.1651x over previous
#include <cuda_runtime.h>
#include <cuda_fp16.h>
#include <stdint.h>

#define NTOK 4096
#define CDIM 64
#define BM   128
#define BN   64
#define NITER (NTOK / BN)       // 64
#define NPROB 18
#define L2E  1.4426950408889634f

// ---------------------------------------------------------------------------
// Device scratch (static __device__ arrays: allocation-free per harness rules)
// Contraction-dim storage is PERMUTED within each 16-element block:
// stored order [0,1,8,9, 2,3,10,11, 4,5,12,13, 6,7,14,15] so that one 8-byte
// load yields an entire MMA fragment register pair (b0,b1)/(a0,a2).
// ---------------------------------------------------------------------------
__device__ __half g_Qhi[3 * 2 * NTOK * CDIM];   // [branch][b][n][c'] * log2e, hi
__device__ __half g_Qlo[3 * 2 * NTOK * CDIM];   // residual lo
__device__ __half g_KThi[3 * 2 * NTOK * CDIM];  // [kstream][b][j][c'], hi
__device__ __half g_KTlo[3 * 2 * NTOK * CDIM];  // lo
__device__ __half g_Vh [3 * 2 * CDIM * NTOK];   // [branch][b][c][j']
__device__ float  g_O  [NPROB * NTOK * CDIM];   // [pidx][i][c] attention out

__device__ __host__ __forceinline__ int perm16(int b) {
    // stored position of original in-block index b (0..15)
    int t = (b & 7) >> 1;
    return 4 * t + ((b >> 3) & 1) * 2 + (b & 1);
}

// ---------------------------------------------------------------------------
// Preprocessing
// ---------------------------------------------------------------------------
__global__ void prep_q(const float* __restrict__ q0, const float* __restrict__ q1,
                       const float* __restrict__ q2) {
    int z = blockIdx.y;
    const float* src = (z == 0) ? q0 : (z == 1) ? q1 : q2;
    int i = blockIdx.x * blockDim.x + threadIdx.x;     // [0, 524288)
    float v = src[i] * L2E;
    __half h = __float2half_rn(v);
    int c = i & 63, n = i >> 6;
    int pc = (c & 48) | perm16(c & 15);
    size_t o = (size_t)z * 2 * NTOK * CDIM + (size_t)n * 64 + pc;
    g_Qhi[o] = h;
    g_Qlo[o] = __float2half_rn(v - __half2float(h));
}

__global__ void prep_v(const float* __restrict__ v0, const float* __restrict__ v1,
                       const float* __restrict__ v2) {
    int z = blockIdx.y;
    const float* src = (z == 0) ? v0 : (z == 1) ? v1 : v2;
    int i = blockIdx.x * blockDim.x + threadIdx.x;
    int j = i & 4095, c = i >> 12;
    int pj = (j & ~15) | perm16(j & 15);
    g_Vh[(size_t)z * 2 * CDIM * NTOK + (size_t)c * NTOK + pj] = __float2half_rn(src[i]);
}

// k [b][c][j] -> kT [j][c'], hi/lo split, c permuted. 32x32 tiles, block (32,8).
__global__ void prep_k(const float* __restrict__ k0, const float* __restrict__ k1,
                       const float* __restrict__ k2) {
    __shared__ float tile[32][33];
    int zb = blockIdx.z;
    int ks = zb >> 1, b = zb & 1;
    const float* src = ((ks == 0) ? k0 : (ks == 1) ? k1 : k2) + (size_t)b * CDIM * NTOK;
    int j0 = blockIdx.x * 32, c0 = blockIdx.y * 32;
    int tx = threadIdx.x, ty = threadIdx.y;
#pragma unroll
    for (int yy = 0; yy < 32; yy += 8)
        tile[ty + yy][tx] = src[(size_t)(c0 + ty + yy) * NTOK + j0 + tx];
    __syncthreads();
    size_t dstbase = ((size_t)ks * 2 + b) * NTOK * CDIM;
    int c = c0 + tx;
    int pc = (c & 48) | perm16(c & 15);
#pragma unroll
    for (int yy = 0; yy < 32; yy += 8) {
        int jl = ty + yy;
        float v = tile[tx][jl];
        __half h = __float2half_rn(v);
        size_t o = dstbase + (size_t)(j0 + jl) * CDIM + pc;
        g_KThi[o] = h;
        g_KTlo[o] = __float2half_rn(v - __half2float(h));
    }
}

// ---------------------------------------------------------------------------
// Fast exp2 (FMA/ALU pipes; avoids MUFU.EX2 throughput wall). x <= 0.
// ---------------------------------------------------------------------------
__device__ __forceinline__ float exp2_fast(float x) {
    x = fmaxf(x, -120.0f);
    float r  = __fadd_rn(x, 12582912.0f);
    float k  = __fadd_rn(r, -12582912.0f);
    int   ik = __float_as_int(r) - 0x4B400000;
    float f  = x - k;                              // [-0.5, 0.5]
    float p  = 1.333355815e-3f;
    p = fmaf(p, f, 9.618129107e-3f);
    p = fmaf(p, f, 5.550410866e-2f);
    p = fmaf(p, f, 2.402265069e-1f);
    p = fmaf(p, f, 6.931471806e-1f);
    p = fmaf(p, f, 1.0f);
    return __int_as_float(__float_as_int(p) + (ik << 23));
}

__device__ __forceinline__ uint32_t pack_h2(float a, float b) {
    __half2 h = __floats2half2_rn(a, b);
    return *reinterpret_cast<uint32_t*>(&h);
}
__device__ __forceinline__ void cp_async16(uint32_t saddr, const void* g) {
    asm volatile("cp.async.cg.shared.global [%0], [%1], 16;" :: "r"(saddr), "l"(g));
}

#define MMA16816(D, A, B0, B1)                                                        \
    asm volatile("mma.sync.aligned.m16n8k16.row.col.f32.f16.f16.f32 "                 \
                 "{%0,%1,%2,%3},{%4,%5,%6,%7},{%8,%9},{%0,%1,%2,%3};"                 \
                 : "+f"((D)[0]), "+f"((D)[1]), "+f"((D)[2]), "+f"((D)[3])             \
                 : "r"((A)[0]), "r"((A)[1]), "r"((A)[2]), "r"((A)[3]),                \
                   "r"(B0), "r"(B1))

// ---------------------------------------------------------------------------
// Flash attention. grid (32 q-tiles, 18 problems), 256 thr (8 warps, 16 q-rows
// each), 2 CTAs/SM. 3-stage cp.async pipeline, one __syncthreads per iter.
// Each 64-col K-tile processed as two 32-col halves (S = 16 regs).
// Smem: 3 stages x 3 tiles x [64][80] half = 92160 B.
// ---------------------------------------------------------------------------
#define ROWH  80                    // padded row stride in halves (LDS.64-conflict-free)
#define TILE_H (64 * ROWH)          // 5120 halves per tile
#define BUF_H  (3 * TILE_H)         // 15360 halves per stage (Khi, Klo, V)
#define SMEM_FLASH (3 * BUF_H * 2)  // 92160 bytes

__global__ void __launch_bounds__(256, 2) flash_kernel() {
    extern __shared__ __half sm[];
    const int tid = threadIdx.x;
    const int wi = tid >> 5, lane = tid & 31;
    const int g = lane >> 2, t = lane & 3;
    const int pidx = blockIdx.y;
    const int br = pidx / 6, rem = pidx % 6;
    const int ks = rem >> 1, b = rem & 1;
    const int i0 = blockIdx.x * BM + wi * 16;

    const size_t qoff = ((size_t)(br * 2 + b)) * NTOK * CDIM;
    const size_t koff = ((size_t)(ks * 2 + b)) * NTOK * CDIM;
    const size_t voff = ((size_t)(br * 2 + b)) * CDIM * NTOK;

    const uint32_t smbase = (uint32_t)__cvta_generic_to_shared(sm);

    // Q fragments (persist; permuted layout -> uint2 per row-half per kc)
    uint32_t qh[4][4], ql[4][4];
    {
        const __half* Qh = g_Qhi + qoff;
        const __half* Ql = g_Qlo + qoff;
#pragma unroll
        for (int kc = 0; kc < 4; kc++) {
            int co = kc * 16 + 4 * t;
            uint2 u;
            u = *reinterpret_cast<const uint2*>(Qh + (size_t)(i0 + g) * 64 + co);
            qh[kc][0] = u.x; qh[kc][2] = u.y;
            u = *reinterpret_cast<const uint2*>(Qh + (size_t)(i0 + g + 8) * 64 + co);
            qh[kc][1] = u.x; qh[kc][3] = u.y;
            u = *reinterpret_cast<const uint2*>(Ql + (size_t)(i0 + g) * 64 + co);
            ql[kc][0] = u.x; ql[kc][2] = u.y;
            u = *reinterpret_cast<const uint2*>(Ql + (size_t)(i0 + g + 8) * 64 + co);
            ql[kc][1] = u.x; ql[kc][3] = u.y;
        }
    }

    float m_a = -1e30f, m_b = -1e30f, l_a = 0.0f, l_b = 0.0f;
    float acc[8][4];
#pragma unroll
    for (int n = 0; n < 8; n++)
#pragma unroll
        for (int q = 0; q < 4; q++) acc[n][q] = 0.0f;

    auto issue = [&](int stage, int jt) {
#pragma unroll
        for (int t3 = 0; t3 < 3; t3++) {
#pragma unroll
            for (int r = 0; r < 2; r++) {
                int v = tid + 256 * r;
                int row = v >> 3, c8 = v & 7;
                int soff = stage * BUF_H + t3 * TILE_H + row * ROWH + c8 * 8;
                const __half* gp;
                if (t3 == 0)      gp = g_KThi + koff + (size_t)(jt + row) * 64 + c8 * 8;
                else if (t3 == 1) gp = g_KTlo + koff + (size_t)(jt + row) * 64 + c8 * 8;
                else              gp = g_Vh  + voff + (size_t)row * NTOK + jt + c8 * 8;
                cp_async16(smbase + soff * 2, gp);
            }
        }
    };

    issue(0, 0);
    asm volatile("cp.async.commit_group;");
    issue(1, BN);
    asm volatile("cp.async.commit_group;");

#pragma unroll 1
    for (int it = 0; it < NITER; it++) {
        if (it < NITER - 1) {
            asm volatile("cp.async.wait_group 1;" ::: "memory");
        } else {
            asm volatile("cp.async.wait_group 0;" ::: "memory");
        }
        __syncthreads();
        // Prefetch stage it+2 AFTER the barrier: all warps finished reading
        // buffer (it+2)%3 == (it-1)%3 during iter it-1, which completed
        // before this barrier (skew < 1 iter).
        if (it < NITER - 2) {
            int nx = it + 2;
            issue(nx % 3, nx * BN);
            asm volatile("cp.async.commit_group;");
        }

        const __half* sKh = sm + (it % 3) * BUF_H;
        const __half* sV  = sKh + 2 * TILE_H;

#pragma unroll
        for (int half = 0; half < 2; half++) {
            float S[4][4];
#pragma unroll
            for (int n = 0; n < 4; n++)
#pragma unroll
                for (int q = 0; q < 4; q++) S[n][q] = 0.0f;

            // GEMM1: S[16 x 32j] = Q[16 x 64c] * K^T (hi/lo split)
#pragma unroll
            for (int kc = 0; kc < 4; kc++) {
#pragma unroll
                for (int n2 = 0; n2 < 4; n2++) {
                    int nc = 4 * half + n2;
                    const __half* kp = sKh + (8 * nc + g) * ROWH + kc * 16 + 4 * t;
                    uint2 bh = *reinterpret_cast<const uint2*>(kp);
                    uint2 bl = *reinterpret_cast<const uint2*>(kp + TILE_H);
                    MMA16816(S[n2], qh[kc], bh.x, bh.y);
                    MMA16816(S[n2], ql[kc], bh.x, bh.y);
                    MMA16816(S[n2], qh[kc], bl.x, bl.y);
                }
            }

            // Online softmax over these 32 columns (base 2)
            float rmax_a = fmaxf(fmaxf(S[0][0], S[0][1]), fmaxf(S[1][0], S[1][1]));
            float rmax_b = fmaxf(fmaxf(S[0][2], S[0][3]), fmaxf(S[1][2], S[1][3]));
            rmax_a = fmaxf(rmax_a, fmaxf(fmaxf(S[2][0], S[2][1]), fmaxf(S[3][0], S[3][1])));
            rmax_b = fmaxf(rmax_b, fmaxf(fmaxf(S[2][2], S[2][3]), fmaxf(S[3][2], S[3][3])));
            rmax_a = fmaxf(rmax_a, __shfl_xor_sync(0xffffffffu, rmax_a, 1));
            rmax_a = fmaxf(rmax_a, __shfl_xor_sync(0xffffffffu, rmax_a, 2));
            rmax_b = fmaxf(rmax_b, __shfl_xor_sync(0xffffffffu, rmax_b, 1));
            rmax_b = fmaxf(rmax_b, __shfl_xor_sync(0xffffffffu, rmax_b, 2));

            float mna = fmaxf(m_a, rmax_a), mnb = fmaxf(m_b, rmax_b);
            float sca = exp2_fast(m_a - mna), scb = exp2_fast(m_b - mnb);
            m_a = mna; m_b = mnb;
            l_a *= sca; l_b *= scb;
#pragma unroll
            for (int nc = 0; nc < 8; nc++) {
                acc[nc][0] *= sca; acc[nc][1] *= sca;
                acc[nc][2] *= scb; acc[nc][3] *= scb;
            }
#pragma unroll
            for (int n2 = 0; n2 < 4; n2++) {
                S[n2][0] = exp2_fast(S[n2][0] - m_a);
                S[n2][1] = exp2_fast(S[n2][1] - m_a);
                S[n2][2] = exp2_fast(S[n2][2] - m_b);
                S[n2][3] = exp2_fast(S[n2][3] - m_b);
                l_a += S[n2][0] + S[n2][1];
                l_b += S[n2][2] + S[n2][3];
            }

            // GEMM2: acc[16 x 64c] += P[16 x 32j] * V^T
#pragma unroll
            for (int kj2 = 0; kj2 < 2; kj2++) {
                int kj = 2 * half + kj2;
                uint32_t pa[4];
                pa[0] = pack_h2(S[2 * kj2][0],     S[2 * kj2][1]);
                pa[1] = pack_h2(S[2 * kj2][2],     S[2 * kj2][3]);
                pa[2] = pack_h2(S[2 * kj2 + 1][0], S[2 * kj2 + 1][1]);
                pa[3] = pack_h2(S[2 * kj2 + 1][2], S[2 * kj2 + 1][3]);
#pragma unroll
                for (int nc = 0; nc < 8; nc++) {
                    const __half* vp = sV + (8 * nc + g) * ROWH + kj * 16 + 4 * t;
                    uint2 vv = *reinterpret_cast<const uint2*>(vp);
                    MMA16816(acc[nc], pa, vv.x, vv.y);
                }
            }
        }
    }

    // Full row denominator = sum across the 4 lanes of the group
    l_a += __shfl_xor_sync(0xffffffffu, l_a, 1);
    l_a += __shfl_xor_sync(0xffffffffu, l_a, 2);
    l_b += __shfl_xor_sync(0xffffffffu, l_b, 1);
    l_b += __shfl_xor_sync(0xffffffffu, l_b, 2);

    // Normalize and dump O tile (fp32, [i][c] with TRUE c indices)
    float ia = 1.0f / l_a, ib = 1.0f / l_b;
    float* Ob = g_O + (size_t)pidx * NTOK * CDIM;
#pragma unroll
    for (int nc = 0; nc < 8; nc++) {
        float2 va = make_float2(acc[nc][0] * ia, acc[nc][1] * ia);
        float2 vb = make_float2(acc[nc][2] * ib, acc[nc][3] * ib);
        *reinterpret_cast<float2*>(&Ob[(size_t)(i0 + g) * 64 + nc * 8 + 2 * t]) = va;
        *reinterpret_cast<float2*>(&Ob[(size_t)(i0 + g + 8) * 64 + nc * 8 + 2 * t]) = vb;
    }
}

// ---------------------------------------------------------------------------
// Epilogue: out[br][b][ks*64+oc][i] = sum_c O[pidx][i][c]*w[oc][c] + bias[oc] + x[b][oc][i]
// ---------------------------------------------------------------------------
__global__ void __launch_bounds__(128) conv_epilogue(
    const float* __restrict__ w0, const float* __restrict__ w1, const float* __restrict__ w2,
    const float* __restrict__ bi0, const float* __restrict__ bi1, const float* __restrict__ bi2,
    const float* __restrict__ x0, const float* __restrict__ x1, const float* __restrict__ x2,
    float* __restrict__ out)
{
    __shared__ __align__(16) float w_s[4096];
    __shared__ float bs[64];
    const int tid = threadIdx.x;
    const int pidx = blockIdx.y;
    const int br = pidx / 6, rem = pidx % 6;
    const int ks = rem >> 1, b = rem & 1;

    const float* w  = (br == 0) ? w0  : (br == 1) ? w1  : w2;
    const float* bi = (br == 0) ? bi0 : (br == 1) ? bi1 : bi2;
    const float* x  = (br == 0) ? x0  : (br == 1) ? x1  : x2;

#pragma unroll
    for (int r = 0; r < 8; r++) {
        int idx4 = tid + 128 * r;
        reinterpret_cast<float4*>(w_s)[idx4] = reinterpret_cast<const float4*>(w)[idx4];
    }
    if (tid < 64) bs[tid] = bi[tid];
    __syncthreads();

    const int i = blockIdx.x * 128 + tid;
    const float* Orow = g_O + (size_t)pidx * NTOK * CDIM + (size_t)i * 64;
    float4 ov[16];
#pragma unroll
    for (int c4 = 0; c4 < 16; c4++)
        ov[c4] = reinterpret_cast<const float4*>(Orow)[c4];

    const float* xr = x + (size_t)b * CDIM * NTOK + i;
    float* orow = out + (size_t)br * (2 * 192 * NTOK) + (size_t)b * (192 * NTOK)
                      + (size_t)ks * (64 * NTOK) + i;

#pragma unroll 4
    for (int oc = 0; oc < 64; oc++) {
        float a = bs[oc];
        const float4* wr = reinterpret_cast<const float4*>(w_s + oc * 64);
#pragma unroll
        for (int c4 = 0; c4 < 16; c4++) {
            float4 w4 = wr[c4];
            a = fmaf(ov[c4].x, w4.x, a);
            a = fmaf(ov[c4].y, w4.y, a);
            a = fmaf(ov[c4].z, w4.z, a);
            a = fmaf(ov[c4].w, w4.w, a);
        }
        orow[(size_t)oc * NTOK] = a + xr[(size_t)oc * NTOK];
    }
}

// ---------------------------------------------------------------------------
// Launch. Inputs in setup_inputs() dict-insertion order.
// ---------------------------------------------------------------------------
extern "C" void kernel_launch(void* const* d_in, const int* in_sizes, int n_in,
                              void* d_out, int out_size) {
    const float* poi_q   = (const float*)d_in[0];
    const float* poi_k   = (const float*)d_in[1];
    const float* poi_v   = (const float*)d_in[2];
    const float* x_poi   = (const float*)d_in[3];
    const float* point_q = (const float*)d_in[4];
    const float* point_k = (const float*)d_in[5];
    const float* point_v = (const float*)d_in[6];
    const float* x_point = (const float*)d_in[7];
    const float* pop_q   = (const float*)d_in[8];
    const float* pop_k   = (const float*)d_in[9];
    const float* pop_v   = (const float*)d_in[10];
    const float* x_pop   = (const float*)d_in[11];
    const float* w_poi   = (const float*)d_in[12];
    const float* b_poi   = (const float*)d_in[13];
    const float* w_point = (const float*)d_in[14];
    const float* b_point = (const float*)d_in[15];
    const float* w_pop   = (const float*)d_in[16];
    const float* b_pop   = (const float*)d_in[17];
    float* out = (float*)d_out;

    cudaFuncSetAttribute(flash_kernel, cudaFuncAttributeMaxDynamicSharedMemorySize,
                         SMEM_FLASH);

    prep_q<<<dim3(2048, 3), 256>>>(poi_q, point_q, pop_q);
    prep_v<<<dim3(2048, 3), 256>>>(poi_v, point_v, pop_v);
    prep_k<<<dim3(128, 2, 6), dim3(32, 8)>>>(poi_k, point_k, pop_k);
    flash_kernel<<<dim3(32, 18), 256, SMEM_FLASH>>>();
    conv_epilogue<<<dim3(32, 18), 128>>>(w_poi, w_point, w_pop,
                                         b_poi, b_point, b_pop,
                                         x_poi, x_point, x_pop, out);
}

// round 9
// speedup vs baseline: 1.2411x; 1.0653x over previous
#include <cuda_runtime.h>
#include <cuda_fp16.h>
#include <stdint.h>

#define NTOK 4096
#define CDIM 64
#define BM   128
#define BN   64
#define NITER (NTOK / BN)       // 64
#define NPROB 18
#define L2E  1.4426950408889634f

// ---------------------------------------------------------------------------
// Device scratch. Contraction-dim storage uses the MMA-fragment permutation
// within each 16-block: stored group 4t..4t+3 = original {2t,2t+1,2t+8,2t+9},
// so an 8-byte load = one (b0,b1) fragment pair.
// K stores hi|lo interleaved per fragment: row = 128 halves,
//   offset(c,sel) = (c>>4)*32 + t(c)*8 + sel*4 + inner(c).
// ---------------------------------------------------------------------------
__device__ __half g_Qhi[3 * 2 * NTOK * CDIM];   // [br][b][n][c'] * log2e, hi
__device__ __half g_Qlo[3 * 2 * NTOK * CDIM];   // residual lo
__device__ __half g_KT [3 * 2 * NTOK * 2 * CDIM]; // [ks][b][j][128] hi|lo interleaved
__device__ __half g_Vh [3 * 2 * CDIM * NTOK];   // [br][b][c][j']

__device__ __host__ __forceinline__ int perm16(int c) {
    int t = (c & 7) >> 1;
    return 4 * t + ((c >> 3) & 1) * 2 + (c & 1);
}

// ---------------------------------------------------------------------------
// Preprocessing
// ---------------------------------------------------------------------------
__global__ void prep_q(const float* __restrict__ q0, const float* __restrict__ q1,
                       const float* __restrict__ q2) {
    int z = blockIdx.y;
    const float* src = (z == 0) ? q0 : (z == 1) ? q1 : q2;
    int i = blockIdx.x * blockDim.x + threadIdx.x;     // [0, 524288)
    float v = src[i] * L2E;
    __half h = __float2half_rn(v);
    int c = i & 63, n = i >> 6;
    int pc = (c & 48) | perm16(c & 15);
    size_t o = (size_t)z * 2 * NTOK * CDIM + (size_t)n * 64 + pc;
    g_Qhi[o] = h;
    g_Qlo[o] = __float2half_rn(v - __half2float(h));
}

__global__ void prep_v(const float* __restrict__ v0, const float* __restrict__ v1,
                       const float* __restrict__ v2) {
    int z = blockIdx.y;
    const float* src = (z == 0) ? v0 : (z == 1) ? v1 : v2;
    int i = blockIdx.x * blockDim.x + threadIdx.x;
    int j = i & 4095, c = i >> 12;
    int pj = (j & ~15) | perm16(j & 15);
    g_Vh[(size_t)z * 2 * CDIM * NTOK + (size_t)c * NTOK + pj] = __float2half_rn(src[i]);
}

// k [b][c][j] -> interleaved kT [j][off(c,sel)]. 32x32 tiles, block (32,8).
__global__ void prep_k(const float* __restrict__ k0, const float* __restrict__ k1,
                       const float* __restrict__ k2) {
    __shared__ float tile[32][33];
    int zb = blockIdx.z;
    int ks = zb >> 1, b = zb & 1;
    const float* src = ((ks == 0) ? k0 : (ks == 1) ? k1 : k2) + (size_t)b * CDIM * NTOK;
    int j0 = blockIdx.x * 32, c0 = blockIdx.y * 32;
    int tx = threadIdx.x, ty = threadIdx.y;
#pragma unroll
    for (int yy = 0; yy < 32; yy += 8)
        tile[ty + yy][tx] = src[(size_t)(c0 + ty + yy) * NTOK + j0 + tx];
    __syncthreads();
    size_t dstbase = ((size_t)ks * 2 + b) * NTOK * 2 * CDIM;
    int c = c0 + tx;
    int base = (c >> 4) * 32 + (((c & 7) >> 1)) * 8 + (((c >> 3) & 1)) * 2 + (c & 1);
#pragma unroll
    for (int yy = 0; yy < 32; yy += 8) {
        int jl = ty + yy;
        float v = tile[tx][jl];
        __half h = __float2half_rn(v);
        size_t o = dstbase + (size_t)(j0 + jl) * 128 + base;
        g_KT[o] = h;                                   // hi at sel=0
        g_KT[o + 4] = __float2half_rn(v - __half2float(h));  // lo at sel=1
    }
}

// ---------------------------------------------------------------------------
// Fast exp2 (FMA pipe). x <= 0 expected; clamped.
// ---------------------------------------------------------------------------
__device__ __forceinline__ float exp2_fast(float x) {
    x = fmaxf(x, -120.0f);
    float r  = __fadd_rn(x, 12582912.0f);
    float k  = __fadd_rn(r, -12582912.0f);
    int   ik = __float_as_int(r) - 0x4B400000;
    float f  = x - k;                              // [-0.5, 0.5]
    float p  = 9.618129107e-3f;
    p = fmaf(p, f, 5.550410866e-2f);
    p = fmaf(p, f, 2.402265069e-1f);
    p = fmaf(p, f, 6.931471806e-1f);
    p = fmaf(p, f, 1.0f);
    return __int_as_float(__float_as_int(p) + (ik << 23));
}

__device__ __forceinline__ uint32_t pack_h2(float a, float b) {
    __half2 h = __floats2half2_rn(a, b);
    return *reinterpret_cast<uint32_t*>(&h);
}
__device__ __forceinline__ void cp_async16(uint32_t saddr, const void* g) {
    asm volatile("cp.async.cg.shared.global [%0], [%1], 16;" :: "r"(saddr), "l"(g));
}

#define MMA16816(D, A, B0, B1)                                                        \
    asm volatile("mma.sync.aligned.m16n8k16.row.col.f32.f16.f16.f32 "                 \
                 "{%0,%1,%2,%3},{%4,%5,%6,%7},{%8,%9},{%0,%1,%2,%3};"                 \
                 : "+f"((D)[0]), "+f"((D)[1]), "+f"((D)[2]), "+f"((D)[3])             \
                 : "r"((A)[0]), "r"((A)[1]), "r"((A)[2]), "r"((A)[3]),                \
                   "r"(B0), "r"(B1))

// f16-accumulate variant (C/D = 2x half2). Used for the small correction terms.
#define MMA16816H(C, A, B0, B1)                                                       \
    asm volatile("mma.sync.aligned.m16n8k16.row.col.f16.f16.f16.f16 "                 \
                 "{%0,%1},{%2,%3,%4,%5},{%6,%7},{%0,%1};"                             \
                 : "+r"((C)[0]), "+r"((C)[1])                                         \
                 : "r"((A)[0]), "r"((A)[1]), "r"((A)[2]), "r"((A)[3]),                \
                   "r"(B0), "r"(B1))

// ---------------------------------------------------------------------------
// Flash attention + fused conv epilogue.
// grid (32 q-tiles, 18 problems), 256 thr (8 warps x 16 q-rows), 2 CTAs/SM.
// Smem per stage: K interleaved 64x160 halves (20480B) + V 64x80 (10240B).
// ---------------------------------------------------------------------------
#define KROWH 160                   // K row stride (halves); 320B = 16 banks mod 32
#define VROWH 80                    // V row stride (halves)
#define KTILE_H (64 * KROWH)        // 10240
#define VTILE_H (64 * VROWH)        // 5120
#define BUF_H  (KTILE_H + VTILE_H)  // 15360 halves per stage
#define SMEM_FLASH (3 * BUF_H * 2)  // 92160 bytes

__global__ void __launch_bounds__(256, 2) flash_kernel(
    const float* __restrict__ w0, const float* __restrict__ w1, const float* __restrict__ w2,
    const float* __restrict__ bi0, const float* __restrict__ bi1, const float* __restrict__ bi2,
    const float* __restrict__ x0, const float* __restrict__ x1, const float* __restrict__ x2,
    float* __restrict__ out)
{
    extern __shared__ __half sm[];
    const int tid = threadIdx.x;
    const int wi = tid >> 5, lane = tid & 31;
    const int g = lane >> 2, t = lane & 3;
    const int pidx = blockIdx.y;
    const int br = pidx / 6, rem = pidx % 6;
    const int ks = rem >> 1, b = rem & 1;
    const int i0 = blockIdx.x * BM + wi * 16;

    const size_t qoff = ((size_t)(br * 2 + b)) * NTOK * CDIM;
    const size_t koff = ((size_t)(ks * 2 + b)) * NTOK * 2 * CDIM;
    const size_t voff = ((size_t)(br * 2 + b)) * CDIM * NTOK;

    const uint32_t smbase = (uint32_t)__cvta_generic_to_shared(sm);

    // Q fragments (persist)
    uint32_t qh[4][4], ql[4][4];
    {
        const __half* Qh = g_Qhi + qoff;
        const __half* Ql = g_Qlo + qoff;
#pragma unroll
        for (int kc = 0; kc < 4; kc++) {
            int co = kc * 16 + 4 * t;
            uint2 u;
            u = *reinterpret_cast<const uint2*>(Qh + (size_t)(i0 + g) * 64 + co);
            qh[kc][0] = u.x; qh[kc][2] = u.y;
            u = *reinterpret_cast<const uint2*>(Qh + (size_t)(i0 + g + 8) * 64 + co);
            qh[kc][1] = u.x; qh[kc][3] = u.y;
            u = *reinterpret_cast<const uint2*>(Ql + (size_t)(i0 + g) * 64 + co);
            ql[kc][0] = u.x; ql[kc][2] = u.y;
            u = *reinterpret_cast<const uint2*>(Ql + (size_t)(i0 + g + 8) * 64 + co);
            ql[kc][1] = u.x; ql[kc][3] = u.y;
        }
    }

    float m_a = -1e30f, m_b = -1e30f, l_a = 0.0f, l_b = 0.0f;
    float acc[8][4];
#pragma unroll
    for (int n = 0; n < 8; n++)
#pragma unroll
        for (int q = 0; q < 4; q++) acc[n][q] = 0.0f;

    auto issue = [&](int stage, int jt) {
        // K: 64 rows x 128 halves = 1024 16B-chunks
#pragma unroll
        for (int r = 0; r < 4; r++) {
            int idx = tid + 256 * r;
            int row = idx >> 4, c16 = idx & 15;
            int soff = stage * BUF_H + row * KROWH + c16 * 8;
            const __half* gp = g_KT + koff + (size_t)(jt + row) * 128 + c16 * 8;
            cp_async16(smbase + soff * 2, gp);
        }
        // V: 64 rows x 64 halves = 512 chunks
#pragma unroll
        for (int r = 0; r < 2; r++) {
            int idx = tid + 256 * r;
            int row = idx >> 3, c8 = idx & 7;
            int soff = stage * BUF_H + KTILE_H + row * VROWH + c8 * 8;
            const __half* gp = g_Vh + voff + (size_t)row * NTOK + jt + c8 * 8;
            cp_async16(smbase + soff * 2, gp);
        }
    };

    issue(0, 0);
    asm volatile("cp.async.commit_group;");
    issue(1, BN);
    asm volatile("cp.async.commit_group;");

#pragma unroll 1
    for (int it = 0; it < NITER; it++) {
        if (it < NITER - 1) {
            asm volatile("cp.async.wait_group 1;" ::: "memory");
        } else {
            asm volatile("cp.async.wait_group 0;" ::: "memory");
        }
        __syncthreads();
        if (it < NITER - 2) {
            int nx = it + 2;
            issue(nx % 3, nx * BN);
            asm volatile("cp.async.commit_group;");
        }

        const __half* sK = sm + (it % 3) * BUF_H;
        const __half* sV = sK + KTILE_H;

#pragma unroll
        for (int half = 0; half < 2; half++) {
            float S[4][4];
            uint32_t corr[4][2];
#pragma unroll
            for (int n = 0; n < 4; n++) {
                S[n][0] = S[n][1] = S[n][2] = S[n][3] = 0.0f;
                corr[n][0] = corr[n][1] = 0u;
            }

            // GEMM1: main (f32 acc) + corrections (f16 acc)
#pragma unroll
            for (int kc = 0; kc < 4; kc++) {
#pragma unroll
                for (int n2 = 0; n2 < 4; n2++) {
                    int nc = 4 * half + n2;
                    const __half* kp = sK + (8 * nc + g) * KROWH + kc * 32 + t * 8;
                    uint4 kb = *reinterpret_cast<const uint4*>(kp);
                    MMA16816(S[n2], qh[kc], kb.x, kb.y);       // qh*kh -> f32
                    MMA16816H(corr[n2], ql[kc], kb.x, kb.y);   // ql*kh -> f16
                    MMA16816H(corr[n2], qh[kc], kb.z, kb.w);   // qh*kl -> f16
                }
            }
            // merge corrections
#pragma unroll
            for (int n2 = 0; n2 < 4; n2++) {
                float2 lo = __half22float2(*reinterpret_cast<__half2*>(&corr[n2][0]));
                float2 hi = __half22float2(*reinterpret_cast<__half2*>(&corr[n2][1]));
                S[n2][0] += lo.x; S[n2][1] += lo.y;
                S[n2][2] += hi.x; S[n2][3] += hi.y;
            }

            // Online softmax over 32 cols (base 2)
            float rmax_a = fmaxf(fmaxf(S[0][0], S[0][1]), fmaxf(S[1][0], S[1][1]));
            float rmax_b = fmaxf(fmaxf(S[0][2], S[0][3]), fmaxf(S[1][2], S[1][3]));
            rmax_a = fmaxf(rmax_a, fmaxf(fmaxf(S[2][0], S[2][1]), fmaxf(S[3][0], S[3][1])));
            rmax_b = fmaxf(rmax_b, fmaxf(fmaxf(S[2][2], S[2][3]), fmaxf(S[3][2], S[3][3])));
            rmax_a = fmaxf(rmax_a, __shfl_xor_sync(0xffffffffu, rmax_a, 1));
            rmax_a = fmaxf(rmax_a, __shfl_xor_sync(0xffffffffu, rmax_a, 2));
            rmax_b = fmaxf(rmax_b, __shfl_xor_sync(0xffffffffu, rmax_b, 1));
            rmax_b = fmaxf(rmax_b, __shfl_xor_sync(0xffffffffu, rmax_b, 2));

            float mna = fmaxf(m_a, rmax_a), mnb = fmaxf(m_b, rmax_b);
            float sca = exp2_fast(m_a - mna), scb = exp2_fast(m_b - mnb);
            m_a = mna; m_b = mnb;
            l_a *= sca; l_b *= scb;
#pragma unroll
            for (int nc = 0; nc < 8; nc++) {
                acc[nc][0] *= sca; acc[nc][1] *= sca;
                acc[nc][2] *= scb; acc[nc][3] *= scb;
            }
#pragma unroll
            for (int n2 = 0; n2 < 4; n2++) {
                S[n2][0] = exp2_fast(S[n2][0] - m_a);
                S[n2][1] = exp2_fast(S[n2][1] - m_a);
                S[n2][2] = exp2_fast(S[n2][2] - m_b);
                S[n2][3] = exp2_fast(S[n2][3] - m_b);
                l_a += S[n2][0] + S[n2][1];
                l_b += S[n2][2] + S[n2][3];
            }

            // GEMM2: acc += P * V^T
#pragma unroll
            for (int kj2 = 0; kj2 < 2; kj2++) {
                int kj = 2 * half + kj2;
                uint32_t pa[4];
                pa[0] = pack_h2(S[2 * kj2][0],     S[2 * kj2][1]);
                pa[1] = pack_h2(S[2 * kj2][2],     S[2 * kj2][3]);
                pa[2] = pack_h2(S[2 * kj2 + 1][0], S[2 * kj2 + 1][1]);
                pa[3] = pack_h2(S[2 * kj2 + 1][2], S[2 * kj2 + 1][3]);
#pragma unroll
                for (int nc = 0; nc < 8; nc++) {
                    const __half* vp = sV + (8 * nc + g) * VROWH + kj * 16 + 4 * t;
                    uint2 vv = *reinterpret_cast<const uint2*>(vp);
                    MMA16816(acc[nc], pa, vv.x, vv.y);
                }
            }
        }
    }

    // Row denominators: sum partials across the 4 t-lanes of each group
    l_a += __shfl_xor_sync(0xffffffffu, l_a, 1);
    l_a += __shfl_xor_sync(0xffffffffu, l_a, 2);
    l_b += __shfl_xor_sync(0xffffffffu, l_b, 1);
    l_b += __shfl_xor_sync(0xffffffffu, l_b, 2);
    float ia = 1.0f / l_a, ib = 1.0f / l_b;

    // ---------------- Fused conv epilogue ----------------
    const float* w  = (br == 0) ? w0  : (br == 1) ? w1  : w2;
    const float* bi = (br == 0) ? bi0 : (br == 1) ? bi1 : bi2;
    const float* x  = (br == 0) ? x0  : (br == 1) ? x1  : x2;

    __syncthreads();   // all reads of pipeline smem done; reuse stage 0
    __half* ws = sm;                       // [64][80] halves, c permuted
    float*  bsf = (float*)(sm + 64 * VROWH);
#pragma unroll
    for (int r = 0; r < 16; r++) {
        int idx = tid + 256 * r;           // 4096 weights
        int oc = idx >> 6, c = idx & 63;
        ws[oc * VROWH + (c & 48) + perm16(c & 15)] = __float2half_rn(w[idx]);
    }
    if (tid < 64) bsf[tid] = bi[tid];
    __syncthreads();

    // A fragments = normalized O (same repacking pattern as P)
    uint32_t oa[4][4];
#pragma unroll
    for (int kc = 0; kc < 4; kc++) {
        oa[kc][0] = pack_h2(acc[2 * kc][0] * ia,     acc[2 * kc][1] * ia);
        oa[kc][1] = pack_h2(acc[2 * kc][2] * ib,     acc[2 * kc][3] * ib);
        oa[kc][2] = pack_h2(acc[2 * kc + 1][0] * ia, acc[2 * kc + 1][1] * ia);
        oa[kc][3] = pack_h2(acc[2 * kc + 1][2] * ib, acc[2 * kc + 1][3] * ib);
    }

    float D[8][4];
#pragma unroll
    for (int n = 0; n < 8; n++) D[n][0] = D[n][1] = D[n][2] = D[n][3] = 0.0f;
#pragma unroll
    for (int kc = 0; kc < 4; kc++) {
#pragma unroll
        for (int nw = 0; nw < 8; nw++) {
            const __half* wp = ws + (8 * nw + g) * VROWH + kc * 16 + 4 * t;
            uint2 wb = *reinterpret_cast<const uint2*>(wp);
            MMA16816(D[nw], oa[kc], wb.x, wb.y);
        }
    }

    // out[br][b][ks*64+oc][i] = D + bias[oc] + x[b][oc][i]
    float* ob = out + (size_t)br * (2 * 192 * NTOK) + (size_t)b * (192 * NTOK)
                    + (size_t)ks * (64 * NTOK);
    const float* xb = x + (size_t)b * CDIM * NTOK;
#pragma unroll
    for (int nw = 0; nw < 8; nw++) {
        int oc = 8 * nw + 2 * t;
        float bs0 = bsf[oc], bs1 = bsf[oc + 1];
        size_t o00 = (size_t)oc * NTOK + i0 + g;
        ob[o00]            = D[nw][0] + bs0 + xb[o00];
        ob[o00 + NTOK]     = D[nw][1] + bs1 + xb[o00 + NTOK];
        size_t o10 = o00 + 8;
        ob[o10]            = D[nw][2] + bs0 + xb[o10];
        ob[o10 + NTOK]     = D[nw][3] + bs1 + xb[o10 + NTOK];
    }
}

// ---------------------------------------------------------------------------
// Launch. Inputs in setup_inputs() dict-insertion order.
// ---------------------------------------------------------------------------
extern "C" void kernel_launch(void* const* d_in, const int* in_sizes, int n_in,
                              void* d_out, int out_size) {
    const float* poi_q   = (const float*)d_in[0];
    const float* poi_k   = (const float*)d_in[1];
    const float* poi_v   = (const float*)d_in[2];
    const float* x_poi   = (const float*)d_in[3];
    const float* point_q = (const float*)d_in[4];
    const float* point_k = (const float*)d_in[5];
    const float* point_v = (const float*)d_in[6];
    const float* x_point = (const float*)d_in[7];
    const float* pop_q   = (const float*)d_in[8];
    const float* pop_k   = (const float*)d_in[9];
    const float* pop_v   = (const float*)d_in[10];
    const float* x_pop   = (const float*)d_in[11];
    const float* w_poi   = (const float*)d_in[12];
    const float* b_poi   = (const float*)d_in[13];
    const float* w_point = (const float*)d_in[14];
    const float* b_point = (const float*)d_in[15];
    const float* w_pop   = (const float*)d_in[16];
    const float* b_pop   = (const float*)d_in[17];
    float* out = (float*)d_out;

    cudaFuncSetAttribute(flash_kernel, cudaFuncAttributeMaxDynamicSharedMemorySize,
                         SMEM_FLASH);

    prep_q<<<dim3(2048, 3), 256>>>(poi_q, point_q, pop_q);
    prep_v<<<dim3(2048, 3), 256>>>(poi_v, point_v, pop_v);
    prep_k<<<dim3(128, 2, 6), dim3(32, 8)>>>(poi_k, point_k, pop_k);
    flash_kernel<<<dim3(32, 18), 256, SMEM_FLASH>>>(
        w_poi, w_point, w_pop, b_poi, b_point, b_pop,
        x_poi, x_point, x_pop, out);
}

// round 11
// speedup vs baseline: 1.2421x; 1.0008x over previous
#include <cuda_runtime.h>
#include <cuda_fp16.h>
#include <stdint.h>

#define NTOK 4096
#define CDIM 64
#define BM   128
#define BN   64
#define NITER (NTOK / BN)       // 64
#define NPROB 18
#define L2E  1.4426950408889634f

// ---------------------------------------------------------------------------
// Device scratch. Contraction-dim storage uses the MMA-fragment permutation
// within each 16-block: stored group 4t..4t+3 = original {2t,2t+1,2t+8,2t+9},
// so an 8-byte load = one (b0,b1) fragment pair.
// K stores hi|lo interleaved per fragment: row = 128 halves,
//   offset(c,sel) = (c>>4)*32 + t(c)*8 + sel*4 + inner(c).
// ---------------------------------------------------------------------------
__device__ __half g_Qhi[3 * 2 * NTOK * CDIM];   // [br][b][n][c'] * log2e, hi
__device__ __half g_Qlo[3 * 2 * NTOK * CDIM];   // residual lo
__device__ __half g_KT [3 * 2 * NTOK * 2 * CDIM]; // [ks][b][j][128] hi|lo interleaved
__device__ __half g_Vh [3 * 2 * CDIM * NTOK];   // [br][b][c][j']

__device__ __host__ __forceinline__ int perm16(int c) {
    int t = (c & 7) >> 1;
    return 4 * t + ((c >> 3) & 1) * 2 + (c & 1);
}

// ---------------------------------------------------------------------------
// Preprocessing
// ---------------------------------------------------------------------------
__global__ void prep_q(const float* __restrict__ q0, const float* __restrict__ q1,
                       const float* __restrict__ q2) {
    int z = blockIdx.y;
    const float* src = (z == 0) ? q0 : (z == 1) ? q1 : q2;
    int i = blockIdx.x * blockDim.x + threadIdx.x;     // [0, 524288)
    float v = src[i] * L2E;
    __half h = __float2half_rn(v);
    int c = i & 63, n = i >> 6;
    int pc = (c & 48) | perm16(c & 15);
    size_t o = (size_t)z * 2 * NTOK * CDIM + (size_t)n * 64 + pc;
    g_Qhi[o] = h;
    g_Qlo[o] = __float2half_rn(v - __half2float(h));
}

__global__ void prep_v(const float* __restrict__ v0, const float* __restrict__ v1,
                       const float* __restrict__ v2) {
    int z = blockIdx.y;
    const float* src = (z == 0) ? v0 : (z == 1) ? v1 : v2;
    int i = blockIdx.x * blockDim.x + threadIdx.x;
    int j = i & 4095, c = i >> 12;
    int pj = (j & ~15) | perm16(j & 15);
    g_Vh[(size_t)z * 2 * CDIM * NTOK + (size_t)c * NTOK + pj] = __float2half_rn(src[i]);
}

// k [b][c][j] -> interleaved kT [j][off(c,sel)]. 32x32 tiles, block (32,8).
__global__ void prep_k(const float* __restrict__ k0, const float* __restrict__ k1,
                       const float* __restrict__ k2) {
    __shared__ float tile[32][33];
    int zb = blockIdx.z;
    int ks = zb >> 1, b = zb & 1;
    const float* src = ((ks == 0) ? k0 : (ks == 1) ? k1 : k2) + (size_t)b * CDIM * NTOK;
    int j0 = blockIdx.x * 32, c0 = blockIdx.y * 32;
    int tx = threadIdx.x, ty = threadIdx.y;
#pragma unroll
    for (int yy = 0; yy < 32; yy += 8)
        tile[ty + yy][tx] = src[(size_t)(c0 + ty + yy) * NTOK + j0 + tx];
    __syncthreads();
    size_t dstbase = ((size_t)ks * 2 + b) * NTOK * 2 * CDIM;
    int c = c0 + tx;
    int base = (c >> 4) * 32 + (((c & 7) >> 1)) * 8 + (((c >> 3) & 1)) * 2 + (c & 1);
#pragma unroll
    for (int yy = 0; yy < 32; yy += 8) {
        int jl = ty + yy;
        float v = tile[tx][jl];
        __half h = __float2half_rn(v);
        size_t o = dstbase + (size_t)(j0 + jl) * 128 + base;
        g_KT[o] = h;                                   // hi at sel=0
        g_KT[o + 4] = __float2half_rn(v - __half2float(h));  // lo at sel=1
    }
}

// ---------------------------------------------------------------------------
// Fast exp2 (FMA pipe). x <= 0 expected; clamped.
// ---------------------------------------------------------------------------
__device__ __forceinline__ float exp2_fast(float x) {
    x = fmaxf(x, -120.0f);
    float r  = __fadd_rn(x, 12582912.0f);
    float k  = __fadd_rn(r, -12582912.0f);
    int   ik = __float_as_int(r) - 0x4B400000;
    float f  = x - k;                              // [-0.5, 0.5]
    float p  = 9.618129107e-3f;
    p = fmaf(p, f, 5.550410866e-2f);
    p = fmaf(p, f, 2.402265069e-1f);
    p = fmaf(p, f, 6.931471806e-1f);
    p = fmaf(p, f, 1.0f);
    return __int_as_float(__float_as_int(p) + (ik << 23));
}

__device__ __forceinline__ uint32_t pack_h2(float a, float b) {
    __half2 h = __floats2half2_rn(a, b);
    return *reinterpret_cast<uint32_t*>(&h);
}
__device__ __forceinline__ void cp_async16(uint32_t saddr, const void* g) {
    asm volatile("cp.async.cg.shared.global [%0], [%1], 16;" :: "r"(saddr), "l"(g));
}

#define MMA16816(D, A, B0, B1)                                                        \
    asm volatile("mma.sync.aligned.m16n8k16.row.col.f32.f16.f16.f32 "                 \
                 "{%0,%1,%2,%3},{%4,%5,%6,%7},{%8,%9},{%0,%1,%2,%3};"                 \
                 : "+f"((D)[0]), "+f"((D)[1]), "+f"((D)[2]), "+f"((D)[3])             \
                 : "r"((A)[0]), "r"((A)[1]), "r"((A)[2]), "r"((A)[3]),                \
                   "r"(B0), "r"(B1))

// f16-accumulate variant (C/D = 2x half2). Used for the small correction terms.
#define MMA16816H(C, A, B0, B1)                                                       \
    asm volatile("mma.sync.aligned.m16n8k16.row.col.f16.f16.f16.f16 "                 \
                 "{%0,%1},{%2,%3,%4,%5},{%6,%7},{%0,%1};"                             \
                 : "+r"((C)[0]), "+r"((C)[1])                                         \
                 : "r"((A)[0]), "r"((A)[1]), "r"((A)[2]), "r"((A)[3]),                \
                   "r"(B0), "r"(B1))

// ---------------------------------------------------------------------------
// Flash attention + fused conv epilogue.
// grid (32 q-tiles, 18 problems), 256 thr (8 warps x 16 q-rows), 2 CTAs/SM.
// Smem per stage: K interleaved 64x160 halves (20480B) + V 64x80 (10240B).
// ---------------------------------------------------------------------------
#define KROWH 160                   // K row stride (halves); 320B = 16 banks mod 32
#define VROWH 80                    // V row stride (halves)
#define KTILE_H (64 * KROWH)        // 10240
#define VTILE_H (64 * VROWH)        // 5120
#define BUF_H  (KTILE_H + VTILE_H)  // 15360 halves per stage
#define SMEM_FLASH (3 * BUF_H * 2)  // 92160 bytes

__global__ void __launch_bounds__(256, 2) flash_kernel(
    const float* __restrict__ w0, const float* __restrict__ w1, const float* __restrict__ w2,
    const float* __restrict__ bi0, const float* __restrict__ bi1, const float* __restrict__ bi2,
    const float* __restrict__ x0, const float* __restrict__ x1, const float* __restrict__ x2,
    float* __restrict__ out)
{
    extern __shared__ __half sm[];
    const int tid = threadIdx.x;
    const int wi = tid >> 5, lane = tid & 31;
    const int g = lane >> 2, t = lane & 3;
    const int pidx = blockIdx.y;
    const int br = pidx / 6, rem = pidx % 6;
    const int ks = rem >> 1, b = rem & 1;
    const int i0 = blockIdx.x * BM + wi * 16;

    const size_t qoff = ((size_t)(br * 2 + b)) * NTOK * CDIM;
    const size_t koff = ((size_t)(ks * 2 + b)) * NTOK * 2 * CDIM;
    const size_t voff = ((size_t)(br * 2 + b)) * CDIM * NTOK;

    const uint32_t smbase = (uint32_t)__cvta_generic_to_shared(sm);

    // Q fragments (persist)
    uint32_t qh[4][4], ql[4][4];
    {
        const __half* Qh = g_Qhi + qoff;
        const __half* Ql = g_Qlo + qoff;
#pragma unroll
        for (int kc = 0; kc < 4; kc++) {
            int co = kc * 16 + 4 * t;
            uint2 u;
            u = *reinterpret_cast<const uint2*>(Qh + (size_t)(i0 + g) * 64 + co);
            qh[kc][0] = u.x; qh[kc][2] = u.y;
            u = *reinterpret_cast<const uint2*>(Qh + (size_t)(i0 + g + 8) * 64 + co);
            qh[kc][1] = u.x; qh[kc][3] = u.y;
            u = *reinterpret_cast<const uint2*>(Ql + (size_t)(i0 + g) * 64 + co);
            ql[kc][0] = u.x; ql[kc][2] = u.y;
            u = *reinterpret_cast<const uint2*>(Ql + (size_t)(i0 + g + 8) * 64 + co);
            ql[kc][1] = u.x; ql[kc][3] = u.y;
        }
    }

    float m_a = -1e30f, m_b = -1e30f, l_a = 0.0f, l_b = 0.0f;
    float acc[8][4];
#pragma unroll
    for (int n = 0; n < 8; n++)
#pragma unroll
        for (int q = 0; q < 4; q++) acc[n][q] = 0.0f;

    auto issue = [&](int stage, int jt) {
        // K: 64 rows x 128 halves = 1024 16B-chunks
#pragma unroll
        for (int r = 0; r < 4; r++) {
            int idx = tid + 256 * r;
            int row = idx >> 4, c16 = idx & 15;
            int soff = stage * BUF_H + row * KROWH + c16 * 8;
            const __half* gp = g_KT + koff + (size_t)(jt + row) * 128 + c16 * 8;
            cp_async16(smbase + soff * 2, gp);
        }
        // V: 64 rows x 64 halves = 512 chunks
#pragma unroll
        for (int r = 0; r < 2; r++) {
            int idx = tid + 256 * r;
            int row = idx >> 3, c8 = idx & 7;
            int soff = stage * BUF_H + KTILE_H + row * VROWH + c8 * 8;
            const __half* gp = g_Vh + voff + (size_t)row * NTOK + jt + c8 * 8;
            cp_async16(smbase + soff * 2, gp);
        }
    };

    issue(0, 0);
    asm volatile("cp.async.commit_group;");
    issue(1, BN);
    asm volatile("cp.async.commit_group;");

#pragma unroll 1
    for (int it = 0; it < NITER; it++) {
        if (it < NITER - 1) {
            asm volatile("cp.async.wait_group 1;" ::: "memory");
        } else {
            asm volatile("cp.async.wait_group 0;" ::: "memory");
        }
        __syncthreads();
        if (it < NITER - 2) {
            int nx = it + 2;
            issue(nx % 3, nx * BN);
            asm volatile("cp.async.commit_group;");
        }

        const __half* sK = sm + (it % 3) * BUF_H;
        const __half* sV = sK + KTILE_H;

#pragma unroll
        for (int half = 0; half < 2; half++) {
            float S[4][4];
            uint32_t corr[4][2];
#pragma unroll
            for (int n = 0; n < 4; n++) {
                S[n][0] = S[n][1] = S[n][2] = S[n][3] = 0.0f;
                corr[n][0] = corr[n][1] = 0u;
            }

            // GEMM1: main (f32 acc) + corrections (f16 acc)
#pragma unroll
            for (int kc = 0; kc < 4; kc++) {
#pragma unroll
                for (int n2 = 0; n2 < 4; n2++) {
                    int nc = 4 * half + n2;
                    const __half* kp = sK + (8 * nc + g) * KROWH + kc * 32 + t * 8;
                    uint4 kb = *reinterpret_cast<const uint4*>(kp);
                    MMA16816(S[n2], qh[kc], kb.x, kb.y);       // qh*kh -> f32
                    MMA16816H(corr[n2], ql[kc], kb.x, kb.y);   // ql*kh -> f16
                    MMA16816H(corr[n2], qh[kc], kb.z, kb.w);   // qh*kl -> f16
                }
            }
            // merge corrections
#pragma unroll
            for (int n2 = 0; n2 < 4; n2++) {
                float2 lo = __half22float2(*reinterpret_cast<__half2*>(&corr[n2][0]));
                float2 hi = __half22float2(*reinterpret_cast<__half2*>(&corr[n2][1]));
                S[n2][0] += lo.x; S[n2][1] += lo.y;
                S[n2][2] += hi.x; S[n2][3] += hi.y;
            }

            // Online softmax over 32 cols (base 2)
            float rmax_a = fmaxf(fmaxf(S[0][0], S[0][1]), fmaxf(S[1][0], S[1][1]));
            float rmax_b = fmaxf(fmaxf(S[0][2], S[0][3]), fmaxf(S[1][2], S[1][3]));
            rmax_a = fmaxf(rmax_a, fmaxf(fmaxf(S[2][0], S[2][1]), fmaxf(S[3][0], S[3][1])));
            rmax_b = fmaxf(rmax_b, fmaxf(fmaxf(S[2][2], S[2][3]), fmaxf(S[3][2], S[3][3])));
            rmax_a = fmaxf(rmax_a, __shfl_xor_sync(0xffffffffu, rmax_a, 1));
            rmax_a = fmaxf(rmax_a, __shfl_xor_sync(0xffffffffu, rmax_a, 2));
            rmax_b = fmaxf(rmax_b, __shfl_xor_sync(0xffffffffu, rmax_b, 1));
            rmax_b = fmaxf(rmax_b, __shfl_xor_sync(0xffffffffu, rmax_b, 2));

            float mna = fmaxf(m_a, rmax_a), mnb = fmaxf(m_b, rmax_b);
            float sca = exp2_fast(m_a - mna), scb = exp2_fast(m_b - mnb);
            m_a = mna; m_b = mnb;
            l_a *= sca; l_b *= scb;
#pragma unroll
            for (int nc = 0; nc < 8; nc++) {
                acc[nc][0] *= sca; acc[nc][1] *= sca;
                acc[nc][2] *= scb; acc[nc][3] *= scb;
            }
#pragma unroll
            for (int n2 = 0; n2 < 4; n2++) {
                S[n2][0] = exp2_fast(S[n2][0] - m_a);
                S[n2][1] = exp2_fast(S[n2][1] - m_a);
                S[n2][2] = exp2_fast(S[n2][2] - m_b);
                S[n2][3] = exp2_fast(S[n2][3] - m_b);
                l_a += S[n2][0] + S[n2][1];
                l_b += S[n2][2] + S[n2][3];
            }

            // GEMM2: acc += P * V^T
#pragma unroll
            for (int kj2 = 0; kj2 < 2; kj2++) {
                int kj = 2 * half + kj2;
                uint32_t pa[4];
                pa[0] = pack_h2(S[2 * kj2][0],     S[2 * kj2][1]);
                pa[1] = pack_h2(S[2 * kj2][2],     S[2 * kj2][3]);
                pa[2] = pack_h2(S[2 * kj2 + 1][0], S[2 * kj2 + 1][1]);
                pa[3] = pack_h2(S[2 * kj2 + 1][2], S[2 * kj2 + 1][3]);
#pragma unroll
                for (int nc = 0; nc < 8; nc++) {
                    const __half* vp = sV + (8 * nc + g) * VROWH + kj * 16 + 4 * t;
                    uint2 vv = *reinterpret_cast<const uint2*>(vp);
                    MMA16816(acc[nc], pa, vv.x, vv.y);
                }
            }
        }
    }

    // Row denominators: sum partials across the 4 t-lanes of each group
    l_a += __shfl_xor_sync(0xffffffffu, l_a, 1);
    l_a += __shfl_xor_sync(0xffffffffu, l_a, 2);
    l_b += __shfl_xor_sync(0xffffffffu, l_b, 1);
    l_b += __shfl_xor_sync(0xffffffffu, l_b, 2);
    float ia = 1.0f / l_a, ib = 1.0f / l_b;

    // ---------------- Fused conv epilogue ----------------
    const float* w  = (br == 0) ? w0  : (br == 1) ? w1  : w2;
    const float* bi = (br == 0) ? bi0 : (br == 1) ? bi1 : bi2;
    const float* x  = (br == 0) ? x0  : (br == 1) ? x1  : x2;

    __syncthreads();   // all reads of pipeline smem done; reuse stage 0
    __half* ws = sm;                       // [64][80] halves, c permuted
    float*  bsf = (float*)(sm + 64 * VROWH);
#pragma unroll
    for (int r = 0; r < 16; r++) {
        int idx = tid + 256 * r;           // 4096 weights
        int oc = idx >> 6, c = idx & 63;
        ws[oc * VROWH + (c & 48) + perm16(c & 15)] = __float2half_rn(w[idx]);
    }
    if (tid < 64) bsf[tid] = bi[tid];
    __syncthreads();

    // A fragments = normalized O (same repacking pattern as P)
    uint32_t oa[4][4];
#pragma unroll
    for (int kc = 0; kc < 4; kc++) {
        oa[kc][0] = pack_h2(acc[2 * kc][0] * ia,     acc[2 * kc][1] * ia);
        oa[kc][1] = pack_h2(acc[2 * kc][2] * ib,     acc[2 * kc][3] * ib);
        oa[kc][2] = pack_h2(acc[2 * kc + 1][0] * ia, acc[2 * kc + 1][1] * ia);
        oa[kc][3] = pack_h2(acc[2 * kc + 1][2] * ib, acc[2 * kc + 1][3] * ib);
    }

    float D[8][4];
#pragma unroll
    for (int n = 0; n < 8; n++) D[n][0] = D[n][1] = D[n][2] = D[n][3] = 0.0f;
#pragma unroll
    for (int kc = 0; kc < 4; kc++) {
#pragma unroll
        for (int nw = 0; nw < 8; nw++) {
            const __half* wp = ws + (8 * nw + g) * VROWH + kc * 16 + 4 * t;
            uint2 wb = *reinterpret_cast<const uint2*>(wp);
            MMA16816(D[nw], oa[kc], wb.x, wb.y);
        }
    }

    // out[br][b][ks*64+oc][i] = D + bias[oc] + x[b][oc][i]
    float* ob = out + (size_t)br * (2 * 192 * NTOK) + (size_t)b * (192 * NTOK)
                    + (size_t)ks * (64 * NTOK);
    const float* xb = x + (size_t)b * CDIM * NTOK;
#pragma unroll
    for (int nw = 0; nw < 8; nw++) {
        int oc = 8 * nw + 2 * t;
        float bs0 = bsf[oc], bs1 = bsf[oc + 1];
        size_t o00 = (size_t)oc * NTOK + i0 + g;
        ob[o00]            = D[nw][0] + bs0 + xb[o00];
        ob[o00 + NTOK]     = D[nw][1] + bs1 + xb[o00 + NTOK];
        size_t o10 = o00 + 8;
        ob[o10]            = D[nw][2] + bs0 + xb[o10];
        ob[o10 + NTOK]     = D[nw][3] + bs1 + xb[o10 + NTOK];
    }
}

// ---------------------------------------------------------------------------
// Launch. Inputs in setup_inputs() dict-insertion order.
// ---------------------------------------------------------------------------
extern "C" void kernel_launch(void* const* d_in, const int* in_sizes, int n_in,
                              void* d_out, int out_size) {
    const float* poi_q   = (const float*)d_in[0];
    const float* poi_k   = (const float*)d_in[1];
    const float* poi_v   = (const float*)d_in[2];
    const float* x_poi   = (const float*)d_in[3];
    const float* point_q = (const float*)d_in[4];
    const float* point_k = (const float*)d_in[5];
    const float* point_v = (const float*)d_in[6];
    const float* x_point = (const float*)d_in[7];
    const float* pop_q   = (const float*)d_in[8];
    const float* pop_k   = (const float*)d_in[9];
    const float* pop_v   = (const float*)d_in[10];
    const float* x_pop   = (const float*)d_in[11];
    const float* w_poi   = (const float*)d_in[12];
    const float* b_poi   = (const float*)d_in[13];
    const float* w_point = (const float*)d_in[14];
    const float* b_point = (const float*)d_in[15];
    const float* w_pop   = (const float*)d_in[16];
    const float* b_pop   = (const float*)d_in[17];
    float* out = (float*)d_out;

    cudaFuncSetAttribute(flash_kernel, cudaFuncAttributeMaxDynamicSharedMemorySize,
                         SMEM_FLASH);

    prep_q<<<dim3(2048, 3), 256>>>(poi_q, point_q, pop_q);
    prep_v<<<dim3(2048, 3), 256>>>(poi_v, point_v, pop_v);
    prep_k<<<dim3(128, 2, 6), dim3(32, 8)>>>(poi_k, point_k, pop_k);
    flash_kernel<<<dim3(32, 18), 256, SMEM_FLASH>>>(
        w_poi, w_point, w_pop, b_poi, b_point, b_pop,
        x_poi, x_point, x_pop, out);
}

// round 13
// speedup vs baseline: 1.2899x; 1.0385x over previous
#include <cuda_runtime.h>
#include <cuda_fp16.h>
#include <stdint.h>

#define NTOK 4096
#define CDIM 64
#define BM   128
#define BN   64
#define NITER (NTOK / BN)       // 64
#define NPROB 18
#define L2E  1.4426950408889634f

// ---------------------------------------------------------------------------
// Device scratch. Contraction-dim storage uses the MMA-fragment permutation
// within each 16-block: stored group 4t..4t+3 = original {2t,2t+1,2t+8,2t+9},
// so an 8-byte load = one (b0,b1) fragment pair.
// K stores hi|lo interleaved per fragment: row = 128 halves,
//   offset(c,sel) = (c>>4)*32 + t(c)*8 + sel*4 + inner(c).
// ---------------------------------------------------------------------------
__device__ __half g_Qhi[3 * 2 * NTOK * CDIM];   // [br][b][n][c'] * log2e, hi
__device__ __half g_Qlo[3 * 2 * NTOK * CDIM];   // residual lo
__device__ __half g_KT [3 * 2 * NTOK * 2 * CDIM]; // [ks][b][j][128] hi|lo interleaved
__device__ __half g_Vh [3 * 2 * CDIM * NTOK];   // [br][b][c][j']

__device__ __host__ __forceinline__ int perm16(int c) {
    int t = (c & 7) >> 1;
    return 4 * t + ((c >> 3) & 1) * 2 + (c & 1);
}

// ---------------------------------------------------------------------------
// Preprocessing
// ---------------------------------------------------------------------------
__global__ void prep_q(const float* __restrict__ q0, const float* __restrict__ q1,
                       const float* __restrict__ q2) {
    int z = blockIdx.y;
    const float* src = (z == 0) ? q0 : (z == 1) ? q1 : q2;
    int i = blockIdx.x * blockDim.x + threadIdx.x;     // [0, 524288)
    float v = src[i] * L2E;
    __half h = __float2half_rn(v);
    int c = i & 63, n = i >> 6;
    int pc = (c & 48) | perm16(c & 15);
    size_t o = (size_t)z * 2 * NTOK * CDIM + (size_t)n * 64 + pc;
    g_Qhi[o] = h;
    g_Qlo[o] = __float2half_rn(v - __half2float(h));
}

__global__ void prep_v(const float* __restrict__ v0, const float* __restrict__ v1,
                       const float* __restrict__ v2) {
    int z = blockIdx.y;
    const float* src = (z == 0) ? v0 : (z == 1) ? v1 : v2;
    int i = blockIdx.x * blockDim.x + threadIdx.x;
    int j = i & 4095, c = i >> 12;
    int pj = (j & ~15) | perm16(j & 15);
    g_Vh[(size_t)z * 2 * CDIM * NTOK + (size_t)c * NTOK + pj] = __float2half_rn(src[i]);
}

// k [b][c][j] -> interleaved kT [j][off(c,sel)]. 32x32 tiles, block (32,8).
__global__ void prep_k(const float* __restrict__ k0, const float* __restrict__ k1,
                       const float* __restrict__ k2) {
    __shared__ float tile[32][33];
    int zb = blockIdx.z;
    int ks = zb >> 1, b = zb & 1;
    const float* src = ((ks == 0) ? k0 : (ks == 1) ? k1 : k2) + (size_t)b * CDIM * NTOK;
    int j0 = blockIdx.x * 32, c0 = blockIdx.y * 32;
    int tx = threadIdx.x, ty = threadIdx.y;
#pragma unroll
    for (int yy = 0; yy < 32; yy += 8)
        tile[ty + yy][tx] = src[(size_t)(c0 + ty + yy) * NTOK + j0 + tx];
    __syncthreads();
    size_t dstbase = ((size_t)ks * 2 + b) * NTOK * 2 * CDIM;
    int c = c0 + tx;
    int base = (c >> 4) * 32 + (((c & 7) >> 1)) * 8 + (((c >> 3) & 1)) * 2 + (c & 1);
#pragma unroll
    for (int yy = 0; yy < 32; yy += 8) {
        int jl = ty + yy;
        float v = tile[tx][jl];
        __half h = __float2half_rn(v);
        size_t o = dstbase + (size_t)(j0 + jl) * 128 + base;
        g_KT[o] = h;                                   // hi at sel=0
        g_KT[o + 4] = __float2half_rn(v - __half2float(h));  // lo at sel=1
    }
}

// ---------------------------------------------------------------------------
// Fast exp2 (FMA pipe). x <= 0 expected; clamped.
// ---------------------------------------------------------------------------
__device__ __forceinline__ float exp2_fast(float x) {
    x = fmaxf(x, -120.0f);
    float r  = __fadd_rn(x, 12582912.0f);
    float k  = __fadd_rn(r, -12582912.0f);
    int   ik = __float_as_int(r) - 0x4B400000;
    float f  = x - k;                              // [-0.5, 0.5]
    float p  = 9.618129107e-3f;
    p = fmaf(p, f, 5.550410866e-2f);
    p = fmaf(p, f, 2.402265069e-1f);
    p = fmaf(p, f, 6.931471806e-1f);
    p = fmaf(p, f, 1.0f);
    return __int_as_float(__float_as_int(p) + (ik << 23));
}

__device__ __forceinline__ uint32_t pack_h2(float a, float b) {
    __half2 h = __floats2half2_rn(a, b);
    return *reinterpret_cast<uint32_t*>(&h);
}
__device__ __forceinline__ void cp_async16(uint32_t saddr, const void* g) {
    asm volatile("cp.async.cg.shared.global [%0], [%1], 16;" :: "r"(saddr), "l"(g));
}

#define MMA16816(D, A, B0, B1)                                                        \
    asm volatile("mma.sync.aligned.m16n8k16.row.col.f32.f16.f16.f32 "                 \
                 "{%0,%1,%2,%3},{%4,%5,%6,%7},{%8,%9},{%0,%1,%2,%3};"                 \
                 : "+f"((D)[0]), "+f"((D)[1]), "+f"((D)[2]), "+f"((D)[3])             \
                 : "r"((A)[0]), "r"((A)[1]), "r"((A)[2]), "r"((A)[3]),                \
                   "r"(B0), "r"(B1))

// f16-accumulate variant (C/D = 2x half2). Used for the small correction terms.
#define MMA16816H(C, A, B0, B1)                                                       \
    asm volatile("mma.sync.aligned.m16n8k16.row.col.f16.f16.f16.f16 "                 \
                 "{%0,%1},{%2,%3,%4,%5},{%6,%7},{%0,%1};"                             \
                 : "+r"((C)[0]), "+r"((C)[1])                                         \
                 : "r"((A)[0]), "r"((A)[1]), "r"((A)[2]), "r"((A)[3]),                \
                   "r"(B0), "r"(B1))

// ---------------------------------------------------------------------------
// Flash attention + fused conv epilogue.
// grid (32 q-tiles, 18 problems), 256 thr (8 warps x 16 q-rows), 2 CTAs/SM.
// Phase-staggered halves: even warps process h0,h1; odd warps h1,h0 — so at
// any instant about half the warps are in MMA phase and half in softmax,
// keeping tensor and FMA pipes simultaneously busy.
// ---------------------------------------------------------------------------
#define KROWH 160                   // K row stride (halves); 320B = 16 banks mod 32
#define VROWH 80                    // V row stride (halves)
#define KTILE_H (64 * KROWH)        // 10240
#define VTILE_H (64 * VROWH)        // 5120
#define BUF_H  (KTILE_H + VTILE_H)  // 15360 halves per stage
#define SMEM_FLASH (3 * BUF_H * 2)  // 92160 bytes

__global__ void __launch_bounds__(256, 2) flash_kernel(
    const float* __restrict__ w0, const float* __restrict__ w1, const float* __restrict__ w2,
    const float* __restrict__ bi0, const float* __restrict__ bi1, const float* __restrict__ bi2,
    const float* __restrict__ x0, const float* __restrict__ x1, const float* __restrict__ x2,
    float* __restrict__ out)
{
    extern __shared__ __half sm[];
    const int tid = threadIdx.x;
    const int wi = tid >> 5, lane = tid & 31;
    const int g = lane >> 2, t = lane & 3;
    const int pidx = blockIdx.y;
    const int br = pidx / 6, rem = pidx % 6;
    const int ks = rem >> 1, b = rem & 1;
    const int i0 = blockIdx.x * BM + wi * 16;
    const int hswap = wi & 1;          // odd warps process halves in reverse order

    const size_t qoff = ((size_t)(br * 2 + b)) * NTOK * CDIM;
    const size_t koff = ((size_t)(ks * 2 + b)) * NTOK * 2 * CDIM;
    const size_t voff = ((size_t)(br * 2 + b)) * CDIM * NTOK;

    const uint32_t smbase = (uint32_t)__cvta_generic_to_shared(sm);

    // Q fragments (persist)
    uint32_t qh[4][4], ql[4][4];
    {
        const __half* Qh = g_Qhi + qoff;
        const __half* Ql = g_Qlo + qoff;
#pragma unroll
        for (int kc = 0; kc < 4; kc++) {
            int co = kc * 16 + 4 * t;
            uint2 u;
            u = *reinterpret_cast<const uint2*>(Qh + (size_t)(i0 + g) * 64 + co);
            qh[kc][0] = u.x; qh[kc][2] = u.y;
            u = *reinterpret_cast<const uint2*>(Qh + (size_t)(i0 + g + 8) * 64 + co);
            qh[kc][1] = u.x; qh[kc][3] = u.y;
            u = *reinterpret_cast<const uint2*>(Ql + (size_t)(i0 + g) * 64 + co);
            ql[kc][0] = u.x; ql[kc][2] = u.y;
            u = *reinterpret_cast<const uint2*>(Ql + (size_t)(i0 + g + 8) * 64 + co);
            ql[kc][1] = u.x; ql[kc][3] = u.y;
        }
    }

    float m_a = -1e30f, m_b = -1e30f, l_a = 0.0f, l_b = 0.0f;
    float acc[8][4];
#pragma unroll
    for (int n = 0; n < 8; n++)
#pragma unroll
        for (int q = 0; q < 4; q++) acc[n][q] = 0.0f;

    auto issue = [&](int stage, int jt) {
        // K: 64 rows x 128 halves = 1024 16B-chunks
#pragma unroll
        for (int r = 0; r < 4; r++) {
            int idx = tid + 256 * r;
            int row = idx >> 4, c16 = idx & 15;
            int soff = stage * BUF_H + row * KROWH + c16 * 8;
            const __half* gp = g_KT + koff + (size_t)(jt + row) * 128 + c16 * 8;
            cp_async16(smbase + soff * 2, gp);
        }
        // V: 64 rows x 64 halves = 512 chunks
#pragma unroll
        for (int r = 0; r < 2; r++) {
            int idx = tid + 256 * r;
            int row = idx >> 3, c8 = idx & 7;
            int soff = stage * BUF_H + KTILE_H + row * VROWH + c8 * 8;
            const __half* gp = g_Vh + voff + (size_t)row * NTOK + jt + c8 * 8;
            cp_async16(smbase + soff * 2, gp);
        }
    };

    issue(0, 0);
    asm volatile("cp.async.commit_group;");
    issue(1, BN);
    asm volatile("cp.async.commit_group;");

#pragma unroll 1
    for (int it = 0; it < NITER; it++) {
        if (it < NITER - 1) {
            asm volatile("cp.async.wait_group 1;" ::: "memory");
        } else {
            asm volatile("cp.async.wait_group 0;" ::: "memory");
        }
        __syncthreads();
        if (it < NITER - 2) {
            int nx = it + 2;
            issue(nx % 3, nx * BN);
            asm volatile("cp.async.commit_group;");
        }

        const __half* sK = sm + (it % 3) * BUF_H;
        const __half* sV = sK + KTILE_H;

#pragma unroll
        for (int h = 0; h < 2; h++) {
            const int half = h ^ hswap;     // stagger phases across warps
            float S[4][4];
            uint32_t corr[4][2];
#pragma unroll
            for (int n = 0; n < 4; n++) {
                S[n][0] = S[n][1] = S[n][2] = S[n][3] = 0.0f;
                corr[n][0] = corr[n][1] = 0u;
            }

            // GEMM1: main (f32 acc) + corrections (f16 acc)
#pragma unroll
            for (int kc = 0; kc < 4; kc++) {
#pragma unroll
                for (int n2 = 0; n2 < 4; n2++) {
                    int nc = 4 * half + n2;
                    const __half* kp = sK + (8 * nc + g) * KROWH + kc * 32 + t * 8;
                    uint4 kb = *reinterpret_cast<const uint4*>(kp);
                    MMA16816(S[n2], qh[kc], kb.x, kb.y);       // qh*kh -> f32
                    MMA16816H(corr[n2], ql[kc], kb.x, kb.y);   // ql*kh -> f16
                    MMA16816H(corr[n2], qh[kc], kb.z, kb.w);   // qh*kl -> f16
                }
            }
            // merge corrections
#pragma unroll
            for (int n2 = 0; n2 < 4; n2++) {
                float2 lo = __half22float2(*reinterpret_cast<__half2*>(&corr[n2][0]));
                float2 hi = __half22float2(*reinterpret_cast<__half2*>(&corr[n2][1]));
                S[n2][0] += lo.x; S[n2][1] += lo.y;
                S[n2][2] += hi.x; S[n2][3] += hi.y;
            }

            // Online softmax over 32 cols (base 2)
            float rmax_a = fmaxf(fmaxf(S[0][0], S[0][1]), fmaxf(S[1][0], S[1][1]));
            float rmax_b = fmaxf(fmaxf(S[0][2], S[0][3]), fmaxf(S[1][2], S[1][3]));
            rmax_a = fmaxf(rmax_a, fmaxf(fmaxf(S[2][0], S[2][1]), fmaxf(S[3][0], S[3][1])));
            rmax_b = fmaxf(rmax_b, fmaxf(fmaxf(S[2][2], S[2][3]), fmaxf(S[3][2], S[3][3])));
            rmax_a = fmaxf(rmax_a, __shfl_xor_sync(0xffffffffu, rmax_a, 1));
            rmax_a = fmaxf(rmax_a, __shfl_xor_sync(0xffffffffu, rmax_a, 2));
            rmax_b = fmaxf(rmax_b, __shfl_xor_sync(0xffffffffu, rmax_b, 1));
            rmax_b = fmaxf(rmax_b, __shfl_xor_sync(0xffffffffu, rmax_b, 2));

            float mna = fmaxf(m_a, rmax_a), mnb = fmaxf(m_b, rmax_b);
            // Warp-vote: skip the 32-FMA accumulator rescale when no row max
            // in this warp moved (the common case once maxes stabilize).
            if (!__all_sync(0xffffffffu, (mna == m_a) & (mnb == m_b))) {
                float sca = exp2_fast(m_a - mna), scb = exp2_fast(m_b - mnb);
                m_a = mna; m_b = mnb;
                l_a *= sca; l_b *= scb;
#pragma unroll
                for (int nc = 0; nc < 8; nc++) {
                    acc[nc][0] *= sca; acc[nc][1] *= sca;
                    acc[nc][2] *= scb; acc[nc][3] *= scb;
                }
            }
#pragma unroll
            for (int n2 = 0; n2 < 4; n2++) {
                S[n2][0] = exp2_fast(S[n2][0] - m_a);
                S[n2][1] = exp2_fast(S[n2][1] - m_a);
                S[n2][2] = exp2_fast(S[n2][2] - m_b);
                S[n2][3] = exp2_fast(S[n2][3] - m_b);
                l_a += S[n2][0] + S[n2][1];
                l_b += S[n2][2] + S[n2][3];
            }

            // GEMM2: acc += P * V^T
#pragma unroll
            for (int kj2 = 0; kj2 < 2; kj2++) {
                int kj = 2 * half + kj2;
                uint32_t pa[4];
                pa[0] = pack_h2(S[2 * kj2][0],     S[2 * kj2][1]);
                pa[1] = pack_h2(S[2 * kj2][2],     S[2 * kj2][3]);
                pa[2] = pack_h2(S[2 * kj2 + 1][0], S[2 * kj2 + 1][1]);
                pa[3] = pack_h2(S[2 * kj2 + 1][2], S[2 * kj2 + 1][3]);
#pragma unroll
                for (int nc = 0; nc < 8; nc++) {
                    const __half* vp = sV + (8 * nc + g) * VROWH + kj * 16 + 4 * t;
                    uint2 vv = *reinterpret_cast<const uint2*>(vp);
                    MMA16816(acc[nc], pa, vv.x, vv.y);
                }
            }
        }
    }

    // Row denominators: sum partials across the 4 t-lanes of each group
    l_a += __shfl_xor_sync(0xffffffffu, l_a, 1);
    l_a += __shfl_xor_sync(0xffffffffu, l_a, 2);
    l_b += __shfl_xor_sync(0xffffffffu, l_b, 1);
    l_b += __shfl_xor_sync(0xffffffffu, l_b, 2);
    float ia = 1.0f / l_a, ib = 1.0f / l_b;

    // ---------------- Fused conv epilogue ----------------
    const float* w  = (br == 0) ? w0  : (br == 1) ? w1  : w2;
    const float* bi = (br == 0) ? bi0 : (br == 1) ? bi1 : bi2;
    const float* x  = (br == 0) ? x0  : (br == 1) ? x1  : x2;

    __syncthreads();   // all reads of pipeline smem done; reuse stage 0
    __half* ws = sm;                       // [64][80] halves, c permuted
    float*  bsf = (float*)(sm + 64 * VROWH);
#pragma unroll
    for (int r = 0; r < 16; r++) {
        int idx = tid + 256 * r;           // 4096 weights
        int oc = idx >> 6, c = idx & 63;
        ws[oc * VROWH + (c & 48) + perm16(c & 15)] = __float2half_rn(w[idx]);
    }
    if (tid < 64) bsf[tid] = bi[tid];
    __syncthreads();

    // A fragments = normalized O (same repacking pattern as P)
    uint32_t oa[4][4];
#pragma unroll
    for (int kc = 0; kc < 4; kc++) {
        oa[kc][0] = pack_h2(acc[2 * kc][0] * ia,     acc[2 * kc][1] * ia);
        oa[kc][1] = pack_h2(acc[2 * kc][2] * ib,     acc[2 * kc][3] * ib);
        oa[kc][2] = pack_h2(acc[2 * kc + 1][0] * ia, acc[2 * kc + 1][1] * ia);
        oa[kc][3] = pack_h2(acc[2 * kc + 1][2] * ib, acc[2 * kc + 1][3] * ib);
    }

    float D[8][4];
#pragma unroll
    for (int n = 0; n < 8; n++) D[n][0] = D[n][1] = D[n][2] = D[n][3] = 0.0f;
#pragma unroll
    for (int kc = 0; kc < 4; kc++) {
#pragma unroll
        for (int nw = 0; nw < 8; nw++) {
            const __half* wp = ws + (8 * nw + g) * VROWH + kc * 16 + 4 * t;
            uint2 wb = *reinterpret_cast<const uint2*>(wp);
            MMA16816(D[nw], oa[kc], wb.x, wb.y);
        }
    }

    // out[br][b][ks*64+oc][i] = D + bias[oc] + x[b][oc][i]
    float* ob = out + (size_t)br * (2 * 192 * NTOK) + (size_t)b * (192 * NTOK)
                    + (size_t)ks * (64 * NTOK);
    const float* xb = x + (size_t)b * CDIM * NTOK;
#pragma unroll
    for (int nw = 0; nw < 8; nw++) {
        int oc = 8 * nw + 2 * t;
        float bs0 = bsf[oc], bs1 = bsf[oc + 1];
        size_t o00 = (size_t)oc * NTOK + i0 + g;
        ob[o00]            = D[nw][0] + bs0 + xb[o00];
        ob[o00 + NTOK]     = D[nw][1] + bs1 + xb[o00 + NTOK];
        size_t o10 = o00 + 8;
        ob[o10]            = D[nw][2] + bs0 + xb[o10];
        ob[o10 + NTOK]     = D[nw][3] + bs1 + xb[o10 + NTOK];
    }
}

// ---------------------------------------------------------------------------
// Launch. Inputs in setup_inputs() dict-insertion order.
// ---------------------------------------------------------------------------
extern "C" void kernel_launch(void* const* d_in, const int* in_sizes, int n_in,
                              void* d_out, int out_size) {
    const float* poi_q   = (const float*)d_in[0];
    const float* poi_k   = (const float*)d_in[1];
    const float* poi_v   = (const float*)d_in[2];
    const float* x_poi   = (const float*)d_in[3];
    const float* point_q = (const float*)d_in[4];
    const float* point_k = (const float*)d_in[5];
    const float* point_v = (const float*)d_in[6];
    const float* x_point = (const float*)d_in[7];
    const float* pop_q   = (const float*)d_in[8];
    const float* pop_k   = (const float*)d_in[9];
    const float* pop_v   = (const float*)d_in[10];
    const float* x_pop   = (const float*)d_in[11];
    const float* w_poi   = (const float*)d_in[12];
    const float* b_poi   = (const float*)d_in[13];
    const float* w_point = (const float*)d_in[14];
    const float* b_point = (const float*)d_in[15];
    const float* w_pop   = (const float*)d_in[16];
    const float* b_pop   = (const float*)d_in[17];
    float* out = (float*)d_out;

    cudaFuncSetAttribute(flash_kernel, cudaFuncAttributeMaxDynamicSharedMemorySize,
                         SMEM_FLASH);

    prep_q<<<dim3(2048, 3), 256>>>(poi_q, point_q, pop_q);
    prep_v<<<dim3(2048, 3), 256>>>(poi_v, point_v, pop_v);
    prep_k<<<dim3(128, 2, 6), dim3(32, 8)>>>(poi_k, point_k, pop_k);
    flash_kernel<<<dim3(32, 18), 256, SMEM_FLASH>>>(
        w_poi, w_point, w_pop, b_poi, b_point, b_pop,
        x_poi, x_point, x_pop, out);
}